// round 2
// baseline (speedup 1.0000x reference)
#include <cuda_runtime.h>
#include <cuda_bf16.h>

#define EMBED   1024
#define S_LEN   2048
#define BATCH   4
#define HEADS   16
#define HDIM    64
#define QKV_DIM 3072   // 3 * EMBED

// Scratch (allocation-free rule: device globals)
__device__ float g_qkv [BATCH * S_LEN * QKV_DIM];  // [B,S,3D]  96 MB
__device__ float g_attn[BATCH * S_LEN * EMBED];    // [B,S,D]   32 MB

// ---------------------------------------------------------------------------
// SGEMM: C[M,N] = A[M,K] @ B[N,K]^T + bias[N]   (both operands K-contiguous)
// 128x128 block tile, BK=8, 256 threads, 8x8 per-thread microtile.
// ---------------------------------------------------------------------------
__global__ __launch_bounds__(256)
void sgemm_nt_bias(int M, int N, int K,
                   const float* __restrict__ A,
                   const float* __restrict__ B,
                   const float* __restrict__ bias,
                   float* __restrict__ C)
{
    __shared__ float As[8][128];   // [k][m]
    __shared__ float Bs[8][128];   // [k][n]

    const int tid = threadIdx.x;
    const int tx  = tid & 15;      // 0..15 -> n microtile
    const int ty  = tid >> 4;      // 0..15 -> m microtile
    const int m0  = blockIdx.y * 128;
    const int n0  = blockIdx.x * 128;

    const int lr = tid >> 1;          // 0..127 tile row
    const int lk = (tid & 1) * 4;     // 0 or 4

    const float* Ag = A + (size_t)(m0 + lr) * K + lk;
    const float* Bg = B + (size_t)(n0 + lr) * K + lk;

    float acc[8][8];
#pragma unroll
    for (int i = 0; i < 8; i++)
#pragma unroll
        for (int j = 0; j < 8; j++) acc[i][j] = 0.f;

    for (int k0 = 0; k0 < K; k0 += 8) {
        float4 a = *(const float4*)(Ag + k0);
        float4 b = *(const float4*)(Bg + k0);
        __syncthreads();
        As[lk + 0][lr] = a.x; As[lk + 1][lr] = a.y;
        As[lk + 2][lr] = a.z; As[lk + 3][lr] = a.w;
        Bs[lk + 0][lr] = b.x; Bs[lk + 1][lr] = b.y;
        Bs[lk + 2][lr] = b.z; Bs[lk + 3][lr] = b.w;
        __syncthreads();
#pragma unroll
        for (int kk = 0; kk < 8; kk++) {
            float ar[8], br[8];
            *(float4*)&ar[0] = *(const float4*)&As[kk][ty * 8];
            *(float4*)&ar[4] = *(const float4*)&As[kk][ty * 8 + 4];
            *(float4*)&br[0] = *(const float4*)&Bs[kk][tx * 8];
            *(float4*)&br[4] = *(const float4*)&Bs[kk][tx * 8 + 4];
#pragma unroll
            for (int i = 0; i < 8; i++)
#pragma unroll
                for (int j = 0; j < 8; j++)
                    acc[i][j] = fmaf(ar[i], br[j], acc[i][j]);
        }
    }

    float bv[8];
#pragma unroll
    for (int j = 0; j < 8; j++) bv[j] = bias[n0 + tx * 8 + j];

#pragma unroll
    for (int i = 0; i < 8; i++) {
        const int m = m0 + ty * 8 + i;
        float* Crow = C + (size_t)m * N + n0 + tx * 8;
        float4 o0 = make_float4(acc[i][0] + bv[0], acc[i][1] + bv[1],
                                acc[i][2] + bv[2], acc[i][3] + bv[3]);
        float4 o1 = make_float4(acc[i][4] + bv[4], acc[i][5] + bv[5],
                                acc[i][6] + bv[6], acc[i][7] + bv[7]);
        *(float4*)(Crow)     = o0;
        *(float4*)(Crow + 4) = o1;
    }
}

// ---------------------------------------------------------------------------
// Fused attention (flash-style, fp32). One CTA per (b, h, 64-row q tile).
// 256 threads, 4x4 microtile over the 64x64 S / O tiles.
// smem: Qs (Q^T, pre-scaled), KPs (K^T, then reused for P^T), Vs. 48 KB total.
// ---------------------------------------------------------------------------
__device__ __forceinline__ float hmax16(float v) {
    v = fmaxf(v, __shfl_xor_sync(0xffffffffu, v, 8));
    v = fmaxf(v, __shfl_xor_sync(0xffffffffu, v, 4));
    v = fmaxf(v, __shfl_xor_sync(0xffffffffu, v, 2));
    v = fmaxf(v, __shfl_xor_sync(0xffffffffu, v, 1));
    return v;
}
__device__ __forceinline__ float hsum16(float v) {
    v += __shfl_xor_sync(0xffffffffu, v, 8);
    v += __shfl_xor_sync(0xffffffffu, v, 4);
    v += __shfl_xor_sync(0xffffffffu, v, 2);
    v += __shfl_xor_sync(0xffffffffu, v, 1);
    return v;
}

__global__ __launch_bounds__(256)
void attn_kernel(const float* __restrict__ qkv, float* __restrict__ out)
{
    __shared__ float Qs [HDIM][64];   // [d][q]   (Q^T, scaled)
    __shared__ float KPs[64][64];     // [d][kv] as K^T, then [kv][q] as P^T
    __shared__ float Vs [64][HDIM];   // [kv][d]

    const int tid = threadIdx.x;
    const int tx  = tid & 15;   // kv / hd microtile
    const int ty  = tid >> 4;   // q microtile
    const int q0  = blockIdx.x * 64;
    const int h   = blockIdx.y;
    const int b   = blockIdx.z;

    // Load Q tile transposed, fold in 1/sqrt(hd)
    const int qbase = (b * S_LEN + q0) * QKV_DIM + h * HDIM;
    for (int f = tid; f < 64 * 16; f += 256) {
        const int r  = f >> 4;
        const int c4 = (f & 15) << 2;
        float4 v = *(const float4*)(qkv + qbase + r * QKV_DIM + c4);
        Qs[c4 + 0][r] = v.x * 0.125f;
        Qs[c4 + 1][r] = v.y * 0.125f;
        Qs[c4 + 2][r] = v.z * 0.125f;
        Qs[c4 + 3][r] = v.w * 0.125f;
    }

    float m_i[4], l_i[4], acc[4][4];
#pragma unroll
    for (int i = 0; i < 4; i++) {
        m_i[i] = -1e30f;
        l_i[i] = 0.f;
#pragma unroll
        for (int j = 0; j < 4; j++) acc[i][j] = 0.f;
    }

    for (int kv0 = 0; kv0 < S_LEN; kv0 += 64) {
        __syncthreads();   // previous iter's PV reads of KPs/Vs complete
        const int kbase = (b * S_LEN + kv0) * QKV_DIM + EMBED + h * HDIM;
        for (int f = tid; f < 64 * 16; f += 256) {
            const int r  = f >> 4;
            const int c4 = (f & 15) << 2;
            float4 k4 = *(const float4*)(qkv + kbase + r * QKV_DIM + c4);
            KPs[c4 + 0][r] = k4.x; KPs[c4 + 1][r] = k4.y;
            KPs[c4 + 2][r] = k4.z; KPs[c4 + 3][r] = k4.w;
            float4 v4 = *(const float4*)(qkv + kbase + EMBED + r * QKV_DIM + c4);
            *(float4*)&Vs[r][c4] = v4;
        }
        __syncthreads();

        // S = (Q*scale) @ K^T  (contraction over d)
        float s[4][4];
#pragma unroll
        for (int i = 0; i < 4; i++)
#pragma unroll
            for (int j = 0; j < 4; j++) s[i][j] = 0.f;
#pragma unroll 8
        for (int d = 0; d < HDIM; d++) {
            float qa[4], kb[4];
            *(float4*)qa = *(const float4*)&Qs[d][ty * 4];
            *(float4*)kb = *(const float4*)&KPs[d][tx * 4];
#pragma unroll
            for (int i = 0; i < 4; i++)
#pragma unroll
                for (int j = 0; j < 4; j++)
                    s[i][j] = fmaf(qa[i], kb[j], s[i][j]);
        }

        // online softmax (rows owned by the 16-lane tx group of each ty)
        float p[4][4];
#pragma unroll
        for (int i = 0; i < 4; i++) {
            float rm = fmaxf(fmaxf(s[i][0], s[i][1]), fmaxf(s[i][2], s[i][3]));
            rm = hmax16(rm);
            const float mnew  = fmaxf(m_i[i], rm);
            const float alpha = __expf(m_i[i] - mnew);
            float rs = 0.f;
#pragma unroll
            for (int j = 0; j < 4; j++) {
                p[i][j] = __expf(s[i][j] - mnew);
                rs += p[i][j];
            }
            rs = hsum16(rs);
            l_i[i] = l_i[i] * alpha + rs;
            m_i[i] = mnew;
#pragma unroll
            for (int j = 0; j < 4; j++) acc[i][j] *= alpha;
        }

        __syncthreads();   // all S-phase reads of KPs done before overwrite
#pragma unroll
        for (int i = 0; i < 4; i++)
#pragma unroll
            for (int j = 0; j < 4; j++)
                KPs[tx * 4 + j][ty * 4 + i] = p[i][j];   // P^T: [kv][q]
        __syncthreads();

        // O += P @ V  (contraction over kv)
#pragma unroll 8
        for (int kv = 0; kv < 64; kv++) {
            float pa[4], vb[4];
            *(float4*)pa = *(const float4*)&KPs[kv][ty * 4];
            *(float4*)vb = *(const float4*)&Vs[kv][tx * 4];
#pragma unroll
            for (int i = 0; i < 4; i++)
#pragma unroll
                for (int j = 0; j < 4; j++)
                    acc[i][j] = fmaf(pa[i], vb[j], acc[i][j]);
        }
    }

    // O / l  ->  [B,S,D] with head offset
#pragma unroll
    for (int i = 0; i < 4; i++) {
        const float inv = 1.f / l_i[i];
        const int q = q0 + ty * 4 + i;
        float* o = out + (size_t)(b * S_LEN + q) * EMBED + h * HDIM + tx * 4;
        *(float4*)o = make_float4(acc[i][0] * inv, acc[i][1] * inv,
                                  acc[i][2] * inv, acc[i][3] * inv);
    }
}

// ---------------------------------------------------------------------------
extern "C" void kernel_launch(void* const* d_in, const int* in_sizes, int n_in,
                              void* d_out, int out_size)
{
    const float* X     = (const float*)d_in[0];   // query (K/V args unused by the math)
    const float* W_qkv = (const float*)d_in[3];   // [3D, D]
    const float* b_qkv = (const float*)d_in[4];   // [3D]
    const float* W_out = (const float*)d_in[5];   // [D, D]
    const float* b_out = (const float*)d_in[6];   // [D]
    float* out = (float*)d_out;

    float *qkv, *attn;
    cudaGetSymbolAddress((void**)&qkv,  g_qkv);
    cudaGetSymbolAddress((void**)&attn, g_attn);

    const int M = BATCH * S_LEN;   // 8192

    {   // QKV projection: [8192,3072] = X @ W_qkv^T + b_qkv
        dim3 grid(QKV_DIM / 128, M / 128);
        sgemm_nt_bias<<<grid, 256>>>(M, QKV_DIM, EMBED, X, W_qkv, b_qkv, qkv);
    }
    {   // fused multi-head attention
        dim3 grid(S_LEN / 64, HEADS, BATCH);
        attn_kernel<<<grid, 256>>>(qkv, attn);
    }
    {   // output projection: [8192,1024] = attn @ W_out^T + b_out
        dim3 grid(EMBED / 128, M / 128);
        sgemm_nt_bias<<<grid, 256>>>(M, EMBED, EMBED, attn, W_out, b_out, out);
    }
}

// round 4
// speedup vs baseline: 1.2875x; 1.2875x over previous
#include <cuda_runtime.h>
#include <cuda_bf16.h>
#include <cstdint>
#include <cstddef>

#define EMBED   1024
#define S_LEN   2048
#define BATCH   4
#define HEADS   16
#define HDIM    64
#define QKV_DIM 3072
#define MTOT    8192          // BATCH * S_LEN
#define K3      3072          // 3 * EMBED (bf16 triplet K)

// ---------------------------------------------------------------------------
// Scratch (device globals; allocation-free rule)
// ---------------------------------------------------------------------------
__device__ __align__(128) float         g_qkv[(size_t)MTOT * QKV_DIM]; // 96 MB
__device__ __align__(128) __nv_bfloat16 g_x3 [(size_t)MTOT * K3];      // 48 MB
__device__ __align__(128) __nv_bfloat16 g_a3 [(size_t)MTOT * K3];      // 48 MB
__device__ __align__(128) __nv_bfloat16 g_wq3[(size_t)QKV_DIM * K3];   // 18 MB
__device__ __align__(128) __nv_bfloat16 g_wo3[(size_t)EMBED * K3];     //  6 MB

// ---------------------------------------------------------------------------
__device__ __forceinline__ uint32_t smem_u32(const void* p) {
    uint32_t a;
    asm("{ .reg .u64 t; cvta.to.shared.u64 t, %1; cvt.u32.u64 %0, t; }" : "=r"(a) : "l"(p));
    return a;
}
__device__ __forceinline__ uint32_t swz(uint32_t off) {      // SW128 xor swizzle
    return off ^ ((off >> 3) & 0x70);
}
__device__ __forceinline__ void ldsm_x4(uint32_t* r, uint32_t addr) {
    asm volatile("ldmatrix.sync.aligned.m8n8.x4.shared.b16 {%0,%1,%2,%3}, [%4];"
                 : "=r"(r[0]), "=r"(r[1]), "=r"(r[2]), "=r"(r[3]) : "r"(addr));
}
__device__ __forceinline__ void mma_bf16(float* d, const uint32_t* a,
                                         uint32_t b0, uint32_t b1) {
    asm volatile(
        "mma.sync.aligned.m16n8k16.row.col.f32.bf16.bf16.f32 "
        "{%0,%1,%2,%3}, {%4,%5,%6,%7}, {%8,%9}, {%0,%1,%2,%3};"
        : "+f"(d[0]), "+f"(d[1]), "+f"(d[2]), "+f"(d[3])
        : "r"(a[0]), "r"(a[1]), "r"(a[2]), "r"(a[3]), "r"(b0), "r"(b1));
}

// ---------------------------------------------------------------------------
// Split kernels: fp32 -> bf16 triplets.
// Activations: [hi, hi, lo]. Weights: [hi, lo, hi].
// per-k dot = ahi*bhi + ahi*blo + alo*bhi  (missing alo*blo ~ 2^-16 rel)
// ---------------------------------------------------------------------------
__global__ void split_act(const float* __restrict__ in, __nv_bfloat16* __restrict__ out, int n) {
    int i = blockIdx.x * blockDim.x + threadIdx.x;
    if (i < n) {
        float x = in[i];
        __nv_bfloat16 hi = __float2bfloat16(x);
        __nv_bfloat16 lo = __float2bfloat16(x - __bfloat162float(hi));
        out[3 * i] = hi; out[3 * i + 1] = hi; out[3 * i + 2] = lo;
    }
}
__global__ void split_wt(const float* __restrict__ in, __nv_bfloat16* __restrict__ out, int n) {
    int i = blockIdx.x * blockDim.x + threadIdx.x;
    if (i < n) {
        float x = in[i];
        __nv_bfloat16 hi = __float2bfloat16(x);
        __nv_bfloat16 lo = __float2bfloat16(x - __bfloat162float(hi));
        out[3 * i] = hi; out[3 * i + 1] = lo; out[3 * i + 2] = hi;
    }
}

// ---------------------------------------------------------------------------
// bf16 tensor-core GEMM (mma.sync):  C[M,N] = A3[M,K3] @ B3[N,K3]^T + bias
// 128x128 CTA tile, BK=64 bf16 (128B rows, SW128 swizzle), 3-stage cp.async.
// 8 warps: 2 (m) x 4 (n); warp tile 64x32; HMMA m16n8k16.
// ---------------------------------------------------------------------------
#define BK         64
#define NIT        (K3 / BK)           // 48
#define TILE_B     (128 * 128)         // 16384 bytes per operand tile
#define STAGE_B    (2 * TILE_B)        // 32 KB
#define GSTAGES    3
#define GEMM_SMEM  (GSTAGES * STAGE_B) // 96 KB

__device__ __forceinline__ void fill_stage(uint32_t sb, int s, int c, int tid,
                                           const __nv_bfloat16* __restrict__ A,
                                           const __nv_bfloat16* __restrict__ B,
                                           int m0, int n0) {
    const uint32_t stage = sb + s * STAGE_B;
#pragma unroll
    for (int i = 0; i < 8; i++) {
        int seg  = i * 256 + tid;        // 0..2047
        int side = seg >> 10;            // 0 = A, 1 = B
        int r    = (seg & 1023) >> 3;    // row 0..127
        int sc   = seg & 7;              // 16B segment within 128B row
        const __nv_bfloat16* src = side ? (B + (size_t)(n0 + r) * K3)
                                        : (A + (size_t)(m0 + r) * K3);
        const char* g = (const char*)(src + c * BK) + sc * 16;
        uint32_t d = stage + side * TILE_B + swz((uint32_t)(r * 128 + sc * 16));
        asm volatile("cp.async.cg.shared.global [%0], [%1], 16;" :: "r"(d), "l"(g));
    }
}

__global__ __launch_bounds__(256)
void gemm_bf16_mma(const __nv_bfloat16* __restrict__ A,
                   const __nv_bfloat16* __restrict__ B,
                   const float* __restrict__ bias,
                   float* __restrict__ C, int N)
{
    extern __shared__ char smem[];
    const uint32_t sb = smem_u32(smem);
    const int tid = threadIdx.x;
    const int wid = tid >> 5, lid = tid & 31;
    const int wm  = wid >> 2;            // 0..1
    const int wn  = wid & 3;             // 0..3
    const int m0  = blockIdx.y * 128;
    const int n0  = blockIdx.x * 128;

    float acc[4][4][4];
#pragma unroll
    for (int mf = 0; mf < 4; mf++)
#pragma unroll
        for (int nf = 0; nf < 4; nf++)
#pragma unroll
            for (int k = 0; k < 4; k++) acc[mf][nf][k] = 0.f;

    // prologue
    fill_stage(sb, 0, 0, tid, A, B, m0, n0);
    asm volatile("cp.async.commit_group;");
    fill_stage(sb, 1, 1, tid, A, B, m0, n0);
    asm volatile("cp.async.commit_group;");

    const uint32_t lrow16 = (uint32_t)(lid & 15) * 128;   // row within 16-row frag
    const uint32_t lseg   = (uint32_t)(lid >> 4) * 16;    // 16B chunk select

    for (int c = 0; c < NIT; c++) {
        const int cn = c + 2;
        if (cn < NIT) fill_stage(sb, cn % GSTAGES, cn, tid, A, B, m0, n0);
        asm volatile("cp.async.commit_group;");
        asm volatile("cp.async.wait_group 2;");
        __syncthreads();

        const uint32_t aBase = sb + (c % GSTAGES) * STAGE_B;
        const uint32_t bBase = aBase + TILE_B;
#pragma unroll
        for (int ks = 0; ks < 4; ks++) {
            const uint32_t koff = (uint32_t)ks * 32 + lseg;
            uint32_t afr[4][4];
#pragma unroll
            for (int mf = 0; mf < 4; mf++)
                ldsm_x4(afr[mf], aBase +
                        swz((uint32_t)(wm * 64 + mf * 16) * 128 + lrow16 + koff));
            uint32_t bfr[2][4];
#pragma unroll
            for (int nh = 0; nh < 2; nh++)
                ldsm_x4(bfr[nh], bBase +
                        swz((uint32_t)(wn * 32 + nh * 16) * 128 + lrow16 + koff));
#pragma unroll
            for (int mf = 0; mf < 4; mf++)
#pragma unroll
                for (int nf = 0; nf < 4; nf++)
                    mma_bf16(acc[mf][nf], afr[mf],
                             bfr[nf >> 1][nf & 1], bfr[nf >> 1][2 + (nf & 1)]);
        }
        __syncthreads();
    }

    // epilogue: add bias, store fp32
#pragma unroll
    for (int mf = 0; mf < 4; mf++) {
        const int row = m0 + wm * 64 + mf * 16 + (lid >> 2);
#pragma unroll
        for (int nf = 0; nf < 4; nf++) {
            const int col = n0 + wn * 32 + nf * 8 + (lid & 3) * 2;
            float2 bv = *(const float2*)(bias + col);
            float2 v0 = make_float2(acc[mf][nf][0] + bv.x, acc[mf][nf][1] + bv.y);
            float2 v1 = make_float2(acc[mf][nf][2] + bv.x, acc[mf][nf][3] + bv.y);
            *(float2*)(C + (size_t)row * N + col)       = v0;
            *(float2*)(C + (size_t)(row + 8) * N + col) = v1;
        }
    }
}

// ---------------------------------------------------------------------------
// Fused attention (flash-style, fp32). Epilogue writes bf16 triplets.
// ---------------------------------------------------------------------------
__device__ __forceinline__ float hmax16(float v) {
    v = fmaxf(v, __shfl_xor_sync(0xffffffffu, v, 8));
    v = fmaxf(v, __shfl_xor_sync(0xffffffffu, v, 4));
    v = fmaxf(v, __shfl_xor_sync(0xffffffffu, v, 2));
    v = fmaxf(v, __shfl_xor_sync(0xffffffffu, v, 1));
    return v;
}
__device__ __forceinline__ float hsum16(float v) {
    v += __shfl_xor_sync(0xffffffffu, v, 8);
    v += __shfl_xor_sync(0xffffffffu, v, 4);
    v += __shfl_xor_sync(0xffffffffu, v, 2);
    v += __shfl_xor_sync(0xffffffffu, v, 1);
    return v;
}

__global__ __launch_bounds__(256)
void attn_kernel(const float* __restrict__ qkv, __nv_bfloat16* __restrict__ out3)
{
    __shared__ float Qs [HDIM][64];
    __shared__ float KPs[64][64];
    __shared__ float Vs [64][HDIM];

    const int tid = threadIdx.x;
    const int tx  = tid & 15;
    const int ty  = tid >> 4;
    const int q0  = blockIdx.x * 64;
    const int h   = blockIdx.y;
    const int b   = blockIdx.z;

    const int qbase = (b * S_LEN + q0) * QKV_DIM + h * HDIM;
    for (int f = tid; f < 64 * 16; f += 256) {
        const int r  = f >> 4;
        const int c4 = (f & 15) << 2;
        float4 v = *(const float4*)(qkv + qbase + r * QKV_DIM + c4);
        Qs[c4 + 0][r] = v.x * 0.125f;
        Qs[c4 + 1][r] = v.y * 0.125f;
        Qs[c4 + 2][r] = v.z * 0.125f;
        Qs[c4 + 3][r] = v.w * 0.125f;
    }

    float m_i[4], l_i[4], acc[4][4];
#pragma unroll
    for (int i = 0; i < 4; i++) {
        m_i[i] = -1e30f; l_i[i] = 0.f;
#pragma unroll
        for (int j = 0; j < 4; j++) acc[i][j] = 0.f;
    }

    for (int kv0 = 0; kv0 < S_LEN; kv0 += 64) {
        __syncthreads();
        const int kbase = (b * S_LEN + kv0) * QKV_DIM + EMBED + h * HDIM;
        for (int f = tid; f < 64 * 16; f += 256) {
            const int r  = f >> 4;
            const int c4 = (f & 15) << 2;
            float4 k4 = *(const float4*)(qkv + kbase + r * QKV_DIM + c4);
            KPs[c4 + 0][r] = k4.x; KPs[c4 + 1][r] = k4.y;
            KPs[c4 + 2][r] = k4.z; KPs[c4 + 3][r] = k4.w;
            float4 v4 = *(const float4*)(qkv + kbase + EMBED + r * QKV_DIM + c4);
            *(float4*)&Vs[r][c4] = v4;
        }
        __syncthreads();

        float s[4][4];
#pragma unroll
        for (int i = 0; i < 4; i++)
#pragma unroll
            for (int j = 0; j < 4; j++) s[i][j] = 0.f;
#pragma unroll 8
        for (int d = 0; d < HDIM; d++) {
            float qa[4], kb[4];
            *(float4*)qa = *(const float4*)&Qs[d][ty * 4];
            *(float4*)kb = *(const float4*)&KPs[d][tx * 4];
#pragma unroll
            for (int i = 0; i < 4; i++)
#pragma unroll
                for (int j = 0; j < 4; j++)
                    s[i][j] = fmaf(qa[i], kb[j], s[i][j]);
        }

        float p[4][4];
#pragma unroll
        for (int i = 0; i < 4; i++) {
            float rm = fmaxf(fmaxf(s[i][0], s[i][1]), fmaxf(s[i][2], s[i][3]));
            rm = hmax16(rm);
            const float mnew  = fmaxf(m_i[i], rm);
            const float alpha = __expf(m_i[i] - mnew);
            float rs = 0.f;
#pragma unroll
            for (int j = 0; j < 4; j++) {
                p[i][j] = __expf(s[i][j] - mnew);
                rs += p[i][j];
            }
            rs = hsum16(rs);
            l_i[i] = l_i[i] * alpha + rs;
            m_i[i] = mnew;
#pragma unroll
            for (int j = 0; j < 4; j++) acc[i][j] *= alpha;
        }

        __syncthreads();
#pragma unroll
        for (int i = 0; i < 4; i++)
#pragma unroll
            for (int j = 0; j < 4; j++)
                KPs[tx * 4 + j][ty * 4 + i] = p[i][j];
        __syncthreads();

#pragma unroll 8
        for (int kv = 0; kv < 64; kv++) {
            float pa[4], vb[4];
            *(float4*)pa = *(const float4*)&KPs[kv][ty * 4];
            *(float4*)vb = *(const float4*)&Vs[kv][tx * 4];
#pragma unroll
            for (int i = 0; i < 4; i++)
#pragma unroll
                for (int j = 0; j < 4; j++)
                    acc[i][j] = fmaf(pa[i], vb[j], acc[i][j]);
        }
    }

#pragma unroll
    for (int i = 0; i < 4; i++) {
        const float inv = 1.f / l_i[i];
        const int q = q0 + ty * 4 + i;
        __nv_bfloat16* o = out3 + (size_t)(b * S_LEN + q) * K3
                                + (size_t)(h * HDIM + tx * 4) * 3;
#pragma unroll
        for (int j = 0; j < 4; j++) {
            float x = acc[i][j] * inv;
            __nv_bfloat16 hi = __float2bfloat16(x);
            __nv_bfloat16 lo = __float2bfloat16(x - __bfloat162float(hi));
            o[3 * j] = hi; o[3 * j + 1] = hi; o[3 * j + 2] = lo;
        }
    }
}

// ---------------------------------------------------------------------------
extern "C" void kernel_launch(void* const* d_in, const int* in_sizes, int n_in,
                              void* d_out, int out_size)
{
    const float* X     = (const float*)d_in[0];
    const float* W_qkv = (const float*)d_in[3];
    const float* b_qkv = (const float*)d_in[4];
    const float* W_out = (const float*)d_in[5];
    const float* b_out = (const float*)d_in[6];
    float* out = (float*)d_out;

    float *qkv; __nv_bfloat16 *x3, *a3, *wq3, *wo3;
    cudaGetSymbolAddress((void**)&qkv, g_qkv);
    cudaGetSymbolAddress((void**)&x3,  g_x3);
    cudaGetSymbolAddress((void**)&a3,  g_a3);
    cudaGetSymbolAddress((void**)&wq3, g_wq3);
    cudaGetSymbolAddress((void**)&wo3, g_wo3);

    cudaFuncSetAttribute(gemm_bf16_mma,
                         cudaFuncAttributeMaxDynamicSharedMemorySize, GEMM_SMEM);

    {   // bf16 triplet splits
        int n1 = MTOT * EMBED;
        split_act<<<(n1 + 255) / 256, 256>>>(X, x3, n1);
        int n2 = QKV_DIM * EMBED;
        split_wt<<<(n2 + 255) / 256, 256>>>(W_qkv, wq3, n2);
        int n3 = EMBED * EMBED;
        split_wt<<<(n3 + 255) / 256, 256>>>(W_out, wo3, n3);
    }
    {   // QKV projection (tensor cores)
        dim3 grid(QKV_DIM / 128, MTOT / 128);
        gemm_bf16_mma<<<grid, 256, GEMM_SMEM>>>(x3, wq3, b_qkv, qkv, QKV_DIM);
    }
    {   // fused attention (fp32), emits bf16 triplets
        dim3 grid(S_LEN / 64, HEADS, BATCH);
        attn_kernel<<<grid, 256>>>(qkv, a3);
    }
    {   // output projection (tensor cores)
        dim3 grid(EMBED / 128, MTOT / 128);
        gemm_bf16_mma<<<grid, 256, GEMM_SMEM>>>(a3, wo3, b_out, out, EMBED);
    }
}

// round 5
// speedup vs baseline: 3.2947x; 2.5590x over previous
#include <cuda_runtime.h>
#include <cuda_bf16.h>
#include <cstdint>
#include <cstddef>

#define EMBED   1024
#define S_LEN   2048
#define BATCH   4
#define HEADS   16
#define HDIM    64
#define QKV_DIM 3072
#define MTOT    8192          // BATCH * S_LEN
#define K3      3072          // 3 * EMBED (bf16 triplet K)

// ---------------------------------------------------------------------------
// Scratch (device globals; allocation-free rule)
// ---------------------------------------------------------------------------
__device__ __align__(128) float         g_qkv[(size_t)MTOT * QKV_DIM]; // 96 MB
__device__ __align__(128) __nv_bfloat16 g_x3 [(size_t)MTOT * K3];      // 48 MB
__device__ __align__(128) __nv_bfloat16 g_a3 [(size_t)MTOT * K3];      // 48 MB
__device__ __align__(128) __nv_bfloat16 g_wq3[(size_t)QKV_DIM * K3];   // 18 MB
__device__ __align__(128) __nv_bfloat16 g_wo3[(size_t)EMBED * K3];     //  6 MB
// head-contiguous attention operands [B*H, S, 64] bf16 (16 MB each)
__device__ __align__(128) __nv_bfloat16 g_Qb[(size_t)MTOT * EMBED];
__device__ __align__(128) __nv_bfloat16 g_Kb[(size_t)MTOT * EMBED];
__device__ __align__(128) __nv_bfloat16 g_Vh[(size_t)MTOT * EMBED];
__device__ __align__(128) __nv_bfloat16 g_Vl[(size_t)MTOT * EMBED];

// ---------------------------------------------------------------------------
__device__ __forceinline__ uint32_t smem_u32(const void* p) {
    uint32_t a;
    asm("{ .reg .u64 t; cvta.to.shared.u64 t, %1; cvt.u32.u64 %0, t; }" : "=r"(a) : "l"(p));
    return a;
}
__device__ __forceinline__ uint32_t swz(uint32_t off) {      // SW128 xor swizzle
    return off ^ ((off >> 3) & 0x70);
}
__device__ __forceinline__ void ldsm_x4(uint32_t* r, uint32_t addr) {
    asm volatile("ldmatrix.sync.aligned.m8n8.x4.shared.b16 {%0,%1,%2,%3}, [%4];"
                 : "=r"(r[0]), "=r"(r[1]), "=r"(r[2]), "=r"(r[3]) : "r"(addr));
}
__device__ __forceinline__ void ldsm_x4_t(uint32_t* r, uint32_t addr) {
    asm volatile("ldmatrix.sync.aligned.m8n8.x4.trans.shared.b16 {%0,%1,%2,%3}, [%4];"
                 : "=r"(r[0]), "=r"(r[1]), "=r"(r[2]), "=r"(r[3]) : "r"(addr));
}
__device__ __forceinline__ void mma_bf16(float* d, const uint32_t* a,
                                         uint32_t b0, uint32_t b1) {
    asm volatile(
        "mma.sync.aligned.m16n8k16.row.col.f32.bf16.bf16.f32 "
        "{%0,%1,%2,%3}, {%4,%5,%6,%7}, {%8,%9}, {%0,%1,%2,%3};"
        : "+f"(d[0]), "+f"(d[1]), "+f"(d[2]), "+f"(d[3])
        : "r"(a[0]), "r"(a[1]), "r"(a[2]), "r"(a[3]), "r"(b0), "r"(b1));
}
// fast exp on fma/alu pipes: exp(x) = 2^(x*log2e), deg-5 poly, rel err ~3e-6
__device__ __forceinline__ float fast_exp(float x) {
    x = fmaxf(x, -80.f);
    float y = x * 1.4426950408889634f;
    float t = y + 12582912.f;                       // round-to-nearest magic
    int   k = __float_as_int(t) - 0x4B400000;
    float f = y - (t - 12582912.f);                 // f in [-0.5, 0.5]
    float c = f * 0.6931471805599453f;
    float p = 1.f + c * (1.f + c * (0.5f + c * (0.166666667f +
                  c * (0.0416666667f + c * 0.00833333f))));
    return __int_as_float(__float_as_int(p) + (k << 23));
}

// ---------------------------------------------------------------------------
// Split kernels: fp32 -> bf16 triplets. Act: [hi,hi,lo]; Wt: [hi,lo,hi].
// ---------------------------------------------------------------------------
__global__ void split_act(const float* __restrict__ in, __nv_bfloat16* __restrict__ out, int n) {
    int i = blockIdx.x * blockDim.x + threadIdx.x;
    if (i < n) {
        float x = in[i];
        __nv_bfloat16 hi = __float2bfloat16(x);
        __nv_bfloat16 lo = __float2bfloat16(x - __bfloat162float(hi));
        out[3 * i] = hi; out[3 * i + 1] = hi; out[3 * i + 2] = lo;
    }
}
__global__ void split_wt(const float* __restrict__ in, __nv_bfloat16* __restrict__ out, int n) {
    int i = blockIdx.x * blockDim.x + threadIdx.x;
    if (i < n) {
        float x = in[i];
        __nv_bfloat16 hi = __float2bfloat16(x);
        __nv_bfloat16 lo = __float2bfloat16(x - __bfloat162float(hi));
        out[3 * i] = hi; out[3 * i + 1] = lo; out[3 * i + 2] = hi;
    }
}

// ---------------------------------------------------------------------------
// prep: g_qkv fp32 [B*S, 3072] -> head-contiguous bf16 Q(scaled)/K/Vhi/Vlo
// ---------------------------------------------------------------------------
__global__ void prep_qkv(const float* __restrict__ qkv,
                         __nv_bfloat16* __restrict__ Qb, __nv_bfloat16* __restrict__ Kb,
                         __nv_bfloat16* __restrict__ Vh, __nv_bfloat16* __restrict__ Vl)
{
    int idx = blockIdx.x * blockDim.x + threadIdx.x;    // MTOT*768 float4 tasks
    if (idx >= MTOT * 768) return;
    int row = idx / 768;
    int c4  = idx % 768;
    float4 v = *(const float4*)(qkv + (size_t)row * QKV_DIM + c4 * 4);
    int col  = c4 * 4;
    int part = col >> 10;
    int hd   = col & 1023;
    int h = hd >> 6, d = hd & 63;
    int b = row >> 11, s = row & 2047;
    size_t o = ((size_t)(b * HEADS + h) * S_LEN + s) * HDIM + d;
    if (part == 0) {
        *(__nv_bfloat162*)(Qb + o)     = __float22bfloat162_rn(make_float2(v.x * 0.125f, v.y * 0.125f));
        *(__nv_bfloat162*)(Qb + o + 2) = __float22bfloat162_rn(make_float2(v.z * 0.125f, v.w * 0.125f));
    } else if (part == 1) {
        *(__nv_bfloat162*)(Kb + o)     = __float22bfloat162_rn(make_float2(v.x, v.y));
        *(__nv_bfloat162*)(Kb + o + 2) = __float22bfloat162_rn(make_float2(v.z, v.w));
    } else {
        __nv_bfloat162 h0 = __float22bfloat162_rn(make_float2(v.x, v.y));
        __nv_bfloat162 h1 = __float22bfloat162_rn(make_float2(v.z, v.w));
        float2 f0 = __bfloat1622float2(h0), f1 = __bfloat1622float2(h1);
        *(__nv_bfloat162*)(Vh + o)     = h0;
        *(__nv_bfloat162*)(Vh + o + 2) = h1;
        *(__nv_bfloat162*)(Vl + o)     = __float22bfloat162_rn(make_float2(v.x - f0.x, v.y - f0.y));
        *(__nv_bfloat162*)(Vl + o + 2) = __float22bfloat162_rn(make_float2(v.z - f1.x, v.w - f1.y));
    }
}

// ---------------------------------------------------------------------------
// bf16 tensor-core GEMM (unchanged from round 4; passing + verified layouts)
// ---------------------------------------------------------------------------
#define BK         64
#define NIT        (K3 / BK)
#define TILE_B     (128 * 128)
#define STAGE_B    (2 * TILE_B)
#define GSTAGES    3
#define GEMM_SMEM  (GSTAGES * STAGE_B)

__device__ __forceinline__ void fill_stage(uint32_t sb, int s, int c, int tid,
                                           const __nv_bfloat16* __restrict__ A,
                                           const __nv_bfloat16* __restrict__ B,
                                           int m0, int n0) {
    const uint32_t stage = sb + s * STAGE_B;
#pragma unroll
    for (int i = 0; i < 8; i++) {
        int seg  = i * 256 + tid;
        int side = seg >> 10;
        int r    = (seg & 1023) >> 3;
        int sc   = seg & 7;
        const __nv_bfloat16* src = side ? (B + (size_t)(n0 + r) * K3)
                                        : (A + (size_t)(m0 + r) * K3);
        const char* g = (const char*)(src + c * BK) + sc * 16;
        uint32_t d = stage + side * TILE_B + swz((uint32_t)(r * 128 + sc * 16));
        asm volatile("cp.async.cg.shared.global [%0], [%1], 16;" :: "r"(d), "l"(g));
    }
}

__global__ __launch_bounds__(256)
void gemm_bf16_mma(const __nv_bfloat16* __restrict__ A,
                   const __nv_bfloat16* __restrict__ B,
                   const float* __restrict__ bias,
                   float* __restrict__ C, int N)
{
    extern __shared__ char smem[];
    const uint32_t sb = smem_u32(smem);
    const int tid = threadIdx.x;
    const int wid = tid >> 5, lid = tid & 31;
    const int wm  = wid >> 2;
    const int wn  = wid & 3;
    const int m0  = blockIdx.y * 128;
    const int n0  = blockIdx.x * 128;

    float acc[4][4][4];
#pragma unroll
    for (int mf = 0; mf < 4; mf++)
#pragma unroll
        for (int nf = 0; nf < 4; nf++)
#pragma unroll
            for (int k = 0; k < 4; k++) acc[mf][nf][k] = 0.f;

    fill_stage(sb, 0, 0, tid, A, B, m0, n0);
    asm volatile("cp.async.commit_group;");
    fill_stage(sb, 1, 1, tid, A, B, m0, n0);
    asm volatile("cp.async.commit_group;");

    const uint32_t lrow16 = (uint32_t)(lid & 15) * 128;
    const uint32_t lseg   = (uint32_t)(lid >> 4) * 16;

    for (int c = 0; c < NIT; c++) {
        const int cn = c + 2;
        if (cn < NIT) fill_stage(sb, cn % GSTAGES, cn, tid, A, B, m0, n0);
        asm volatile("cp.async.commit_group;");
        asm volatile("cp.async.wait_group 2;");
        __syncthreads();

        const uint32_t aBase = sb + (c % GSTAGES) * STAGE_B;
        const uint32_t bBase = aBase + TILE_B;
#pragma unroll
        for (int ks = 0; ks < 4; ks++) {
            const uint32_t koff = (uint32_t)ks * 32 + lseg;
            uint32_t afr[4][4];
#pragma unroll
            for (int mf = 0; mf < 4; mf++)
                ldsm_x4(afr[mf], aBase +
                        swz((uint32_t)(wm * 64 + mf * 16) * 128 + lrow16 + koff));
            uint32_t bfr[2][4];
#pragma unroll
            for (int nh = 0; nh < 2; nh++)
                ldsm_x4(bfr[nh], bBase +
                        swz((uint32_t)(wn * 32 + nh * 16) * 128 + lrow16 + koff));
#pragma unroll
            for (int mf = 0; mf < 4; mf++)
#pragma unroll
                for (int nf = 0; nf < 4; nf++)
                    mma_bf16(acc[mf][nf], afr[mf],
                             bfr[nf >> 1][nf & 1], bfr[nf >> 1][2 + (nf & 1)]);
        }
        __syncthreads();
    }

#pragma unroll
    for (int mf = 0; mf < 4; mf++) {
        const int row = m0 + wm * 64 + mf * 16 + (lid >> 2);
#pragma unroll
        for (int nf = 0; nf < 4; nf++) {
            const int col = n0 + wn * 32 + nf * 8 + (lid & 3) * 2;
            float2 bv = *(const float2*)(bias + col);
            float2 v0 = make_float2(acc[mf][nf][0] + bv.x, acc[mf][nf][1] + bv.y);
            float2 v1 = make_float2(acc[mf][nf][2] + bv.x, acc[mf][nf][3] + bv.y);
            *(float2*)(C + (size_t)row * N + col)       = v0;
            *(float2*)(C + (size_t)(row + 8) * N + col) = v1;
        }
    }
}

// ---------------------------------------------------------------------------
// Tensor-core flash attention.
// CTA: 128 q rows x one (b,h). 8 warps, warp = 16 q rows x full tile.
// kv tiles of 64; K bf16; P,V hi/lo split for PV. Emits bf16 triplets.
// smem: Q 16KB + 3 stages x (K 8KB + Vh 8KB + Vl 8KB) = 88KB.
// ---------------------------------------------------------------------------
#define ATT_STAGE_B 24576
#define ATT_SMEM    (16384 + 3 * ATT_STAGE_B)
#define NKV         (S_LEN / 64)   // 32

__global__ __launch_bounds__(256, 1)
void attn_tc(const __nv_bfloat16* __restrict__ Qb, const __nv_bfloat16* __restrict__ Kb,
             const __nv_bfloat16* __restrict__ Vh, const __nv_bfloat16* __restrict__ Vl,
             __nv_bfloat16* __restrict__ out3)
{
    extern __shared__ char smem[];
    const uint32_t sb = smem_u32(smem);
    const int tid = threadIdx.x, wid = tid >> 5, lid = tid & 31;
    const int q0 = blockIdx.x * 128;
    const int bh = blockIdx.y;
    const size_t hb = (size_t)bh * S_LEN * HDIM;

    // Q tile: 16KB contiguous
    {
        const char* qg = (const char*)(Qb + hb + (size_t)q0 * HDIM);
        for (int i = tid; i < 1024; i += 256) {
            uint32_t d = sb + swz((uint32_t)i * 16);
            asm volatile("cp.async.cg.shared.global [%0], [%1], 16;" :: "r"(d), "l"(qg + i * 16));
        }
        asm volatile("cp.async.commit_group;");
    }
    // K/V stage loader (each tile contiguous 8KB per tensor)
    auto load_kv = [&](int stage, int t) {
        const uint32_t st = sb + 16384 + stage * ATT_STAGE_B;
        const char* kg = (const char*)(Kb + hb + (size_t)t * 64 * HDIM);
        const char* hg = (const char*)(Vh + hb + (size_t)t * 64 * HDIM);
        const char* lg = (const char*)(Vl + hb + (size_t)t * 64 * HDIM);
        for (int i = tid; i < 512; i += 256) {
            uint32_t o = swz((uint32_t)i * 16);
            asm volatile("cp.async.cg.shared.global [%0], [%1], 16;" :: "r"(st + o),         "l"(kg + i * 16));
            asm volatile("cp.async.cg.shared.global [%0], [%1], 16;" :: "r"(st + 8192 + o),  "l"(hg + i * 16));
            asm volatile("cp.async.cg.shared.global [%0], [%1], 16;" :: "r"(st + 16384 + o), "l"(lg + i * 16));
        }
    };
    load_kv(0, 0);
    asm volatile("cp.async.commit_group;");
    load_kv(1, 1);
    asm volatile("cp.async.commit_group;");

    asm volatile("cp.async.wait_group 2;");   // Q done
    __syncthreads();

    const uint32_t lrow = (uint32_t)(lid & 15) * 128;
    const uint32_t lseg = (uint32_t)(lid >> 4) * 16;

    // Q fragments: persistent across all kv tiles
    uint32_t qfr[4][4];
#pragma unroll
    for (int ks = 0; ks < 4; ks++)
        ldsm_x4(qfr[ks], sb + swz((uint32_t)(wid * 16) * 128 + lrow + ks * 32 + lseg));

    float o_acc[8][4];
#pragma unroll
    for (int nf = 0; nf < 8; nf++)
#pragma unroll
        for (int k = 0; k < 4; k++) o_acc[nf][k] = 0.f;
    float m0 = -1e30f, m8 = -1e30f, l0 = 0.f, l8 = 0.f;

    for (int t = 0; t < NKV; t++) {
        if (t + 2 < NKV) load_kv((t + 2) % 3, t + 2);
        asm volatile("cp.async.commit_group;");
        asm volatile("cp.async.wait_group 2;");
        __syncthreads();

        const uint32_t st = sb + 16384 + (t % 3) * ATT_STAGE_B;

        // ---- S = Q @ K^T ----
        float sfr[8][4];
#pragma unroll
        for (int nf = 0; nf < 8; nf++)
#pragma unroll
            for (int k = 0; k < 4; k++) sfr[nf][k] = 0.f;
#pragma unroll
        for (int ks = 0; ks < 4; ks++) {
            uint32_t bfr[4][4];
#pragma unroll
            for (int nh = 0; nh < 4; nh++)
                ldsm_x4(bfr[nh], st + swz((uint32_t)(nh * 16) * 128 + lrow + ks * 32 + lseg));
#pragma unroll
            for (int nf = 0; nf < 8; nf++)
                mma_bf16(sfr[nf], qfr[ks],
                         bfr[nf >> 1][nf & 1], bfr[nf >> 1][2 + (nf & 1)]);
        }

        // ---- online softmax (rows r0 = lid/4, r8 = +8 within warp tile) ----
        float mx0 = -1e30f, mx8 = -1e30f;
#pragma unroll
        for (int j = 0; j < 8; j++) {
            mx0 = fmaxf(mx0, fmaxf(sfr[j][0], sfr[j][1]));
            mx8 = fmaxf(mx8, fmaxf(sfr[j][2], sfr[j][3]));
        }
        mx0 = fmaxf(mx0, __shfl_xor_sync(0xffffffffu, mx0, 1));
        mx0 = fmaxf(mx0, __shfl_xor_sync(0xffffffffu, mx0, 2));
        mx8 = fmaxf(mx8, __shfl_xor_sync(0xffffffffu, mx8, 1));
        mx8 = fmaxf(mx8, __shfl_xor_sync(0xffffffffu, mx8, 2));
        const float mn0 = fmaxf(m0, mx0), mn8 = fmaxf(m8, mx8);
        const float a0 = fast_exp(m0 - mn0), a8 = fast_exp(m8 - mn8);
        m0 = mn0; m8 = mn8;

        uint32_t pr0[8], pr8[8], qr0[8], qr8[8];   // P hi/lo packed bf16x2
        float s0 = 0.f, s8 = 0.f;
#pragma unroll
        for (int j = 0; j < 8; j++) {
            float p0 = fast_exp(sfr[j][0] - mn0);
            float p1 = fast_exp(sfr[j][1] - mn0);
            float p2 = fast_exp(sfr[j][2] - mn8);
            float p3 = fast_exp(sfr[j][3] - mn8);
            s0 += p0 + p1; s8 += p2 + p3;
            __nv_bfloat162 h01 = __float22bfloat162_rn(make_float2(p0, p1));
            __nv_bfloat162 h23 = __float22bfloat162_rn(make_float2(p2, p3));
            float2 f01 = __bfloat1622float2(h01);
            float2 f23 = __bfloat1622float2(h23);
            __nv_bfloat162 l01 = __float22bfloat162_rn(make_float2(p0 - f01.x, p1 - f01.y));
            __nv_bfloat162 l23 = __float22bfloat162_rn(make_float2(p2 - f23.x, p3 - f23.y));
            pr0[j] = *(uint32_t*)&h01; pr8[j] = *(uint32_t*)&h23;
            qr0[j] = *(uint32_t*)&l01; qr8[j] = *(uint32_t*)&l23;
        }
        s0 += __shfl_xor_sync(0xffffffffu, s0, 1);
        s0 += __shfl_xor_sync(0xffffffffu, s0, 2);
        s8 += __shfl_xor_sync(0xffffffffu, s8, 1);
        s8 += __shfl_xor_sync(0xffffffffu, s8, 2);
        l0 = l0 * a0 + s0;
        l8 = l8 * a8 + s8;
#pragma unroll
        for (int nf = 0; nf < 8; nf++) {
            o_acc[nf][0] *= a0; o_acc[nf][1] *= a0;
            o_acc[nf][2] *= a8; o_acc[nf][3] *= a8;
        }

        // ---- O += P @ V  (hi*hi + hi*lo + lo*hi) ----
#pragma unroll
        for (int ks = 0; ks < 4; ks++) {
            uint32_t vh[4][4], vl[4][4];
#pragma unroll
            for (int nh = 0; nh < 4; nh++) {
                const uint32_t ro = swz((uint32_t)(ks * 16) * 128 + lrow + nh * 32 + lseg);
                ldsm_x4_t(vh[nh], st + 8192  + ro);
                ldsm_x4_t(vl[nh], st + 16384 + ro);
            }
            uint32_t ah[4] = {pr0[2 * ks], pr8[2 * ks], pr0[2 * ks + 1], pr8[2 * ks + 1]};
            uint32_t al[4] = {qr0[2 * ks], qr8[2 * ks], qr0[2 * ks + 1], qr8[2 * ks + 1]};
#pragma unroll
            for (int nf = 0; nf < 8; nf++) {
                uint32_t b0 = vh[nf >> 1][(nf & 1) * 2];
                uint32_t b1 = vh[nf >> 1][(nf & 1) * 2 + 1];
                uint32_t c0 = vl[nf >> 1][(nf & 1) * 2];
                uint32_t c1 = vl[nf >> 1][(nf & 1) * 2 + 1];
                mma_bf16(o_acc[nf], ah, b0, b1);
                mma_bf16(o_acc[nf], ah, c0, c1);
                mma_bf16(o_acc[nf], al, b0, b1);
            }
        }
        __syncthreads();
    }

    // ---- epilogue: normalize, write bf16 triplets [hi,hi,lo] ----
    const float i0 = 1.f / l0, i8 = 1.f / l8;
    const int b = bh / HEADS, h = bh % HEADS;
    const int r0g = q0 + wid * 16 + (lid >> 2);
#pragma unroll
    for (int nf = 0; nf < 8; nf++) {
        const int d0 = nf * 8 + (lid & 3) * 2;
#pragma unroll
        for (int e = 0; e < 2; e++) {
            const int d = d0 + e;
            {
                float x = o_acc[nf][e] * i0;
                __nv_bfloat16 hi = __float2bfloat16(x);
                __nv_bfloat16 lo = __float2bfloat16(x - __bfloat162float(hi));
                __nv_bfloat16* o = out3 + (size_t)(b * S_LEN + r0g) * K3 + (size_t)(h * HDIM + d) * 3;
                o[0] = hi; o[1] = hi; o[2] = lo;
            }
            {
                float x = o_acc[nf][2 + e] * i8;
                __nv_bfloat16 hi = __float2bfloat16(x);
                __nv_bfloat16 lo = __float2bfloat16(x - __bfloat162float(hi));
                __nv_bfloat16* o = out3 + (size_t)(b * S_LEN + r0g + 8) * K3 + (size_t)(h * HDIM + d) * 3;
                o[0] = hi; o[1] = hi; o[2] = lo;
            }
        }
    }
}

// ---------------------------------------------------------------------------
extern "C" void kernel_launch(void* const* d_in, const int* in_sizes, int n_in,
                              void* d_out, int out_size)
{
    const float* X     = (const float*)d_in[0];
    const float* W_qkv = (const float*)d_in[3];
    const float* b_qkv = (const float*)d_in[4];
    const float* W_out = (const float*)d_in[5];
    const float* b_out = (const float*)d_in[6];
    float* out = (float*)d_out;

    float *qkv; __nv_bfloat16 *x3, *a3, *wq3, *wo3, *Qb, *Kb, *Vh, *Vl;
    cudaGetSymbolAddress((void**)&qkv, g_qkv);
    cudaGetSymbolAddress((void**)&x3,  g_x3);
    cudaGetSymbolAddress((void**)&a3,  g_a3);
    cudaGetSymbolAddress((void**)&wq3, g_wq3);
    cudaGetSymbolAddress((void**)&wo3, g_wo3);
    cudaGetSymbolAddress((void**)&Qb,  g_Qb);
    cudaGetSymbolAddress((void**)&Kb,  g_Kb);
    cudaGetSymbolAddress((void**)&Vh,  g_Vh);
    cudaGetSymbolAddress((void**)&Vl,  g_Vl);

    cudaFuncSetAttribute(gemm_bf16_mma,
                         cudaFuncAttributeMaxDynamicSharedMemorySize, GEMM_SMEM);
    cudaFuncSetAttribute(attn_tc,
                         cudaFuncAttributeMaxDynamicSharedMemorySize, ATT_SMEM);

    {   // bf16 triplet splits
        int n1 = MTOT * EMBED;
        split_act<<<(n1 + 255) / 256, 256>>>(X, x3, n1);
        int n2 = QKV_DIM * EMBED;
        split_wt<<<(n2 + 255) / 256, 256>>>(W_qkv, wq3, n2);
        int n3 = EMBED * EMBED;
        split_wt<<<(n3 + 255) / 256, 256>>>(W_out, wo3, n3);
    }
    {   // QKV projection (tensor cores)
        dim3 grid(QKV_DIM / 128, MTOT / 128);
        gemm_bf16_mma<<<grid, 256, GEMM_SMEM>>>(x3, wq3, b_qkv, qkv, QKV_DIM);
    }
    {   // fp32 qkv -> head-contiguous bf16 Q/K/Vhi/Vlo
        int n = MTOT * 768;
        prep_qkv<<<(n + 255) / 256, 256>>>(qkv, Qb, Kb, Vh, Vl);
    }
    {   // tensor-core flash attention, emits bf16 triplets
        dim3 grid(S_LEN / 128, BATCH * HEADS);
        attn_tc<<<grid, 256, ATT_SMEM>>>(Qb, Kb, Vh, Vl, a3);
    }
    {   // output projection (tensor cores)
        dim3 grid(EMBED / 128, MTOT / 128);
        gemm_bf16_mma<<<grid, 256, GEMM_SMEM>>>(a3, wo3, b_out, out, EMBED);
    }
}

// round 6
// speedup vs baseline: 4.6749x; 1.4189x over previous
#include <cuda_runtime.h>
#include <cuda_bf16.h>
#include <cstdint>
#include <cstddef>

#define EMBED   1024
#define S_LEN   2048
#define BATCH   4
#define HEADS   16
#define HDIM    64
#define QKV_DIM 3072
#define MTOT    8192          // BATCH * S_LEN

// ---------------------------------------------------------------------------
// Scratch (device globals; allocation-free rule)
// ---------------------------------------------------------------------------
__device__ __align__(128) float g_qkv[(size_t)MTOT * QKV_DIM];   // 96 MB
__device__ __align__(128) float g_xr [(size_t)MTOT * EMBED];     // 32 MB (X, tf32-rounded)
__device__ __align__(128) float g_wqr[(size_t)QKV_DIM * EMBED];  // 12 MB
__device__ __align__(128) float g_wor[(size_t)EMBED * EMBED];    //  4 MB
__device__ __align__(128) float g_att[(size_t)MTOT * EMBED];     // 32 MB (attn out, tf32-rounded)
// head-contiguous attention operands [B*H, S, 64] bf16 (16 MB each)
__device__ __align__(128) __nv_bfloat16 g_Qb[(size_t)MTOT * EMBED];
__device__ __align__(128) __nv_bfloat16 g_Kb[(size_t)MTOT * EMBED];
__device__ __align__(128) __nv_bfloat16 g_Vh[(size_t)MTOT * EMBED];
__device__ __align__(128) __nv_bfloat16 g_Vl[(size_t)MTOT * EMBED];

// ---------------------------------------------------------------------------
__device__ __forceinline__ uint32_t smem_u32(const void* p) {
    uint32_t a;
    asm("{ .reg .u64 t; cvta.to.shared.u64 t, %1; cvt.u32.u64 %0, t; }" : "=r"(a) : "l"(p));
    return a;
}
__device__ __forceinline__ uint32_t swz(uint32_t off) {      // SW128 xor swizzle
    return off ^ ((off >> 3) & 0x70);
}
__device__ __forceinline__ void ldsm_x4(uint32_t* r, uint32_t addr) {
    asm volatile("ldmatrix.sync.aligned.m8n8.x4.shared.b16 {%0,%1,%2,%3}, [%4];"
                 : "=r"(r[0]), "=r"(r[1]), "=r"(r[2]), "=r"(r[3]) : "r"(addr));
}
__device__ __forceinline__ void ldsm_x4_t(uint32_t* r, uint32_t addr) {
    asm volatile("ldmatrix.sync.aligned.m8n8.x4.trans.shared.b16 {%0,%1,%2,%3}, [%4];"
                 : "=r"(r[0]), "=r"(r[1]), "=r"(r[2]), "=r"(r[3]) : "r"(addr));
}
__device__ __forceinline__ void mma_bf16(float* d, const uint32_t* a,
                                         uint32_t b0, uint32_t b1) {
    asm volatile(
        "mma.sync.aligned.m16n8k16.row.col.f32.bf16.bf16.f32 "
        "{%0,%1,%2,%3}, {%4,%5,%6,%7}, {%8,%9}, {%0,%1,%2,%3};"
        : "+f"(d[0]), "+f"(d[1]), "+f"(d[2]), "+f"(d[3])
        : "r"(a[0]), "r"(a[1]), "r"(a[2]), "r"(a[3]), "r"(b0), "r"(b1));
}
__device__ __forceinline__ void mma_tf32(float* d, const uint32_t* a,
                                         uint32_t b0, uint32_t b1) {
    asm volatile(
        "mma.sync.aligned.m16n8k8.row.col.f32.tf32.tf32.f32 "
        "{%0,%1,%2,%3}, {%4,%5,%6,%7}, {%8,%9}, {%0,%1,%2,%3};"
        : "+f"(d[0]), "+f"(d[1]), "+f"(d[2]), "+f"(d[3])
        : "r"(a[0]), "r"(a[1]), "r"(a[2]), "r"(a[3]), "r"(b0), "r"(b1));
}
__device__ __forceinline__ float rna_tf32(float x) {
    uint32_t r;
    asm("cvt.rna.tf32.f32 %0, %1;" : "=r"(r) : "f"(x));
    return __uint_as_float(r);
}
// fast exp on fma/alu pipes (avoids MUFU throughput limit), rel err ~3e-6
__device__ __forceinline__ float fast_exp(float x) {
    x = fmaxf(x, -80.f);
    float y = x * 1.4426950408889634f;
    float t = y + 12582912.f;
    int   k = __float_as_int(t) - 0x4B400000;
    float f = y - (t - 12582912.f);
    float c = f * 0.6931471805599453f;
    float p = 1.f + c * (1.f + c * (0.5f + c * (0.166666667f +
                  c * (0.0416666667f + c * 0.00833333f))));
    return __int_as_float(__float_as_int(p) + (k << 23));
}

// ---------------------------------------------------------------------------
// tf32 pre-rounding (removes truncation bias in mma's implicit conversion)
// ---------------------------------------------------------------------------
__global__ void round_tf32(const float* __restrict__ in, float* __restrict__ out, int n4) {
    int i = blockIdx.x * blockDim.x + threadIdx.x;
    if (i < n4) {
        float4 v = ((const float4*)in)[i];
        v.x = rna_tf32(v.x); v.y = rna_tf32(v.y);
        v.z = rna_tf32(v.z); v.w = rna_tf32(v.w);
        ((float4*)out)[i] = v;
    }
}

// ---------------------------------------------------------------------------
// prep: g_qkv fp32 [B*S, 3072] -> head-contiguous bf16 Q(scaled)/K/Vhi/Vlo
// ---------------------------------------------------------------------------
__global__ void prep_qkv(const float* __restrict__ qkv,
                         __nv_bfloat16* __restrict__ Qb, __nv_bfloat16* __restrict__ Kb,
                         __nv_bfloat16* __restrict__ Vh, __nv_bfloat16* __restrict__ Vl)
{
    int idx = blockIdx.x * blockDim.x + threadIdx.x;
    if (idx >= MTOT * 768) return;
    int row = idx / 768;
    int c4  = idx % 768;
    float4 v = *(const float4*)(qkv + (size_t)row * QKV_DIM + c4 * 4);
    int col  = c4 * 4;
    int part = col >> 10;
    int hd   = col & 1023;
    int h = hd >> 6, d = hd & 63;
    int b = row >> 11, s = row & 2047;
    size_t o = ((size_t)(b * HEADS + h) * S_LEN + s) * HDIM + d;
    if (part == 0) {
        *(__nv_bfloat162*)(Qb + o)     = __float22bfloat162_rn(make_float2(v.x * 0.125f, v.y * 0.125f));
        *(__nv_bfloat162*)(Qb + o + 2) = __float22bfloat162_rn(make_float2(v.z * 0.125f, v.w * 0.125f));
    } else if (part == 1) {
        *(__nv_bfloat162*)(Kb + o)     = __float22bfloat162_rn(make_float2(v.x, v.y));
        *(__nv_bfloat162*)(Kb + o + 2) = __float22bfloat162_rn(make_float2(v.z, v.w));
    } else {
        __nv_bfloat162 h0 = __float22bfloat162_rn(make_float2(v.x, v.y));
        __nv_bfloat162 h1 = __float22bfloat162_rn(make_float2(v.z, v.w));
        float2 f0 = __bfloat1622float2(h0), f1 = __bfloat1622float2(h1);
        *(__nv_bfloat162*)(Vh + o)     = h0;
        *(__nv_bfloat162*)(Vh + o + 2) = h1;
        *(__nv_bfloat162*)(Vl + o)     = __float22bfloat162_rn(make_float2(v.x - f0.x, v.y - f0.y));
        *(__nv_bfloat162*)(Vl + o + 2) = __float22bfloat162_rn(make_float2(v.z - f1.x, v.w - f1.y));
    }
}

// ---------------------------------------------------------------------------
// tf32 tensor-core GEMM:  C[M,N] = A[M,1024] @ B[N,1024]^T + bias  (fp32 I/O,
// inputs pre-rounded to tf32). 128x128 CTA tile, BK=32 floats (128B rows,
// SW128), 3-stage cp.async, single sync/iter, double-buffered fragments.
// 8 warps 2(m) x 4(n); warp tile 64x32; mma m16n8k8.
// ---------------------------------------------------------------------------
#define GK         1024
#define BKF        32
#define NITF       (GK / BKF)          // 32
#define TILE_B     16384               // 128 rows * 128 B
#define STAGE_B    (2 * TILE_B)
#define GSTAGES    3
#define GEMM_SMEM  (GSTAGES * STAGE_B) // 96 KB

__device__ __forceinline__ void fill_stage_f(uint32_t sb, int s, int c, int tid,
                                             const float* __restrict__ A,
                                             const float* __restrict__ B,
                                             int m0, int n0) {
    const uint32_t stage = sb + s * STAGE_B;
#pragma unroll
    for (int i = 0; i < 8; i++) {
        int seg  = i * 256 + tid;
        int side = seg >> 10;
        int r    = (seg & 1023) >> 3;
        int sc   = seg & 7;
        const float* src = side ? (B + (size_t)(n0 + r) * GK)
                                : (A + (size_t)(m0 + r) * GK);
        const char* g = (const char*)(src + c * BKF) + sc * 16;
        uint32_t d = stage + side * TILE_B + swz((uint32_t)(r * 128 + sc * 16));
        asm volatile("cp.async.cg.shared.global [%0], [%1], 16;" :: "r"(d), "l"(g));
    }
}

__global__ __launch_bounds__(256)
void gemm_tf32_mma(const float* __restrict__ A,
                   const float* __restrict__ B,
                   const float* __restrict__ bias,
                   float* __restrict__ C, int N)
{
    extern __shared__ char smem[];
    const uint32_t sb = smem_u32(smem);
    const int tid = threadIdx.x;
    const int wid = tid >> 5, lid = tid & 31;
    const int wm  = wid >> 2;
    const int wn  = wid & 3;
    const int m0  = blockIdx.y * 128;
    const int n0  = blockIdx.x * 128;

    float acc[4][4][4];
#pragma unroll
    for (int mf = 0; mf < 4; mf++)
#pragma unroll
        for (int nf = 0; nf < 4; nf++)
#pragma unroll
            for (int k = 0; k < 4; k++) acc[mf][nf][k] = 0.f;

    fill_stage_f(sb, 0, 0, tid, A, B, m0, n0);
    asm volatile("cp.async.commit_group;");
    fill_stage_f(sb, 1, 1, tid, A, B, m0, n0);
    asm volatile("cp.async.commit_group;");

    const uint32_t lrow = (uint32_t)(lid & 15) * 128;
    const uint32_t lseg = (uint32_t)(lid >> 4) * 16;

    uint32_t afr[2][4][4], bfr[2][2][4];

    for (int c = 0; c < NITF; c++) {
        asm volatile("cp.async.wait_group 1;");
        __syncthreads();
        const int cn = c + 2;
        if (cn < NITF) fill_stage_f(sb, cn % GSTAGES, cn, tid, A, B, m0, n0);
        asm volatile("cp.async.commit_group;");

        const uint32_t aBase = sb + (c % GSTAGES) * STAGE_B;
        const uint32_t bBase = aBase + TILE_B;

        // load k8-slice 0 fragments
#pragma unroll
        for (int mf = 0; mf < 4; mf++)
            ldsm_x4(afr[0][mf], aBase + swz((uint32_t)(wm * 64 + mf * 16) * 128 + lrow + lseg));
#pragma unroll
        for (int nh = 0; nh < 2; nh++)
            ldsm_x4(bfr[0][nh], bBase + swz((uint32_t)(wn * 32 + nh * 16) * 128 + lrow + lseg));

#pragma unroll
        for (int ks = 0; ks < 4; ks++) {
            if (ks < 3) {   // prefetch next slice into other buffer
                const uint32_t koff = (uint32_t)(ks + 1) * 32 + lseg;
                const int nb = (ks + 1) & 1;
#pragma unroll
                for (int mf = 0; mf < 4; mf++)
                    ldsm_x4(afr[nb][mf], aBase + swz((uint32_t)(wm * 64 + mf * 16) * 128 + lrow + koff));
#pragma unroll
                for (int nh = 0; nh < 2; nh++)
                    ldsm_x4(bfr[nb][nh], bBase + swz((uint32_t)(wn * 32 + nh * 16) * 128 + lrow + koff));
            }
            const int cb = ks & 1;
#pragma unroll
            for (int mf = 0; mf < 4; mf++)
#pragma unroll
                for (int nf = 0; nf < 4; nf++)
                    mma_tf32(acc[mf][nf], afr[cb][mf],
                             bfr[cb][nf >> 1][nf & 1], bfr[cb][nf >> 1][2 + (nf & 1)]);
        }
    }
    __syncthreads();

#pragma unroll
    for (int mf = 0; mf < 4; mf++) {
        const int row = m0 + wm * 64 + mf * 16 + (lid >> 2);
#pragma unroll
        for (int nf = 0; nf < 4; nf++) {
            const int col = n0 + wn * 32 + nf * 8 + (lid & 3) * 2;
            float2 bv = *(const float2*)(bias + col);
            float2 v0 = make_float2(acc[mf][nf][0] + bv.x, acc[mf][nf][1] + bv.y);
            float2 v1 = make_float2(acc[mf][nf][2] + bv.x, acc[mf][nf][3] + bv.y);
            *(float2*)(C + (size_t)row * N + col)       = v0;
            *(float2*)(C + (size_t)(row + 8) * N + col) = v1;
        }
    }
}

// ---------------------------------------------------------------------------
// Tensor-core flash attention (bf16 QK, hi/lo-split PV). Single sync per kv
// tile. Epilogue writes tf32-rounded fp32 [B*S, 1024] for the tf32 out-proj.
// ---------------------------------------------------------------------------
#define ATT_STAGE_B 24576
#define ATT_SMEM    (16384 + 3 * ATT_STAGE_B)
#define NKV         (S_LEN / 64)   // 32

__global__ __launch_bounds__(256, 1)
void attn_tc(const __nv_bfloat16* __restrict__ Qb, const __nv_bfloat16* __restrict__ Kb,
             const __nv_bfloat16* __restrict__ Vh, const __nv_bfloat16* __restrict__ Vl,
             float* __restrict__ outf)
{
    extern __shared__ char smem[];
    const uint32_t sb = smem_u32(smem);
    const int tid = threadIdx.x, wid = tid >> 5, lid = tid & 31;
    const int q0 = blockIdx.x * 128;
    const int bh = blockIdx.y;
    const size_t hb = (size_t)bh * S_LEN * HDIM;

    {   // Q tile: 16KB contiguous
        const char* qg = (const char*)(Qb + hb + (size_t)q0 * HDIM);
        for (int i = tid; i < 1024; i += 256) {
            uint32_t d = sb + swz((uint32_t)i * 16);
            asm volatile("cp.async.cg.shared.global [%0], [%1], 16;" :: "r"(d), "l"(qg + i * 16));
        }
        asm volatile("cp.async.commit_group;");
    }
    auto load_kv = [&](int stage, int t) {
        const uint32_t st = sb + 16384 + stage * ATT_STAGE_B;
        const char* kg = (const char*)(Kb + hb + (size_t)t * 64 * HDIM);
        const char* hg = (const char*)(Vh + hb + (size_t)t * 64 * HDIM);
        const char* lg = (const char*)(Vl + hb + (size_t)t * 64 * HDIM);
        for (int i = tid; i < 512; i += 256) {
            uint32_t o = swz((uint32_t)i * 16);
            asm volatile("cp.async.cg.shared.global [%0], [%1], 16;" :: "r"(st + o),         "l"(kg + i * 16));
            asm volatile("cp.async.cg.shared.global [%0], [%1], 16;" :: "r"(st + 8192 + o),  "l"(hg + i * 16));
            asm volatile("cp.async.cg.shared.global [%0], [%1], 16;" :: "r"(st + 16384 + o), "l"(lg + i * 16));
        }
    };
    load_kv(0, 0);
    asm volatile("cp.async.commit_group;");
    load_kv(1, 1);
    asm volatile("cp.async.commit_group;");

    asm volatile("cp.async.wait_group 2;");   // Q ready
    __syncthreads();

    const uint32_t lrow = (uint32_t)(lid & 15) * 128;
    const uint32_t lseg = (uint32_t)(lid >> 4) * 16;

    uint32_t qfr[4][4];
#pragma unroll
    for (int ks = 0; ks < 4; ks++)
        ldsm_x4(qfr[ks], sb + swz((uint32_t)(wid * 16) * 128 + lrow + ks * 32 + lseg));

    float o_acc[8][4];
#pragma unroll
    for (int nf = 0; nf < 8; nf++)
#pragma unroll
        for (int k = 0; k < 4; k++) o_acc[nf][k] = 0.f;
    float m0 = -1e30f, m8 = -1e30f, l0 = 0.f, l8 = 0.f;

    for (int t = 0; t < NKV; t++) {
        asm volatile("cp.async.wait_group 1;");
        __syncthreads();
        if (t + 2 < NKV) load_kv((t + 2) % 3, t + 2);
        asm volatile("cp.async.commit_group;");

        const uint32_t st = sb + 16384 + (t % 3) * ATT_STAGE_B;

        // ---- S = Q @ K^T ----
        float sfr[8][4];
#pragma unroll
        for (int nf = 0; nf < 8; nf++)
#pragma unroll
            for (int k = 0; k < 4; k++) sfr[nf][k] = 0.f;
#pragma unroll
        for (int ks = 0; ks < 4; ks++) {
            uint32_t bfr[4][4];
#pragma unroll
            for (int nh = 0; nh < 4; nh++)
                ldsm_x4(bfr[nh], st + swz((uint32_t)(nh * 16) * 128 + lrow + ks * 32 + lseg));
#pragma unroll
            for (int nf = 0; nf < 8; nf++)
                mma_bf16(sfr[nf], qfr[ks],
                         bfr[nf >> 1][nf & 1], bfr[nf >> 1][2 + (nf & 1)]);
        }

        // ---- online softmax ----
        float mx0 = -1e30f, mx8 = -1e30f;
#pragma unroll
        for (int j = 0; j < 8; j++) {
            mx0 = fmaxf(mx0, fmaxf(sfr[j][0], sfr[j][1]));
            mx8 = fmaxf(mx8, fmaxf(sfr[j][2], sfr[j][3]));
        }
        mx0 = fmaxf(mx0, __shfl_xor_sync(0xffffffffu, mx0, 1));
        mx0 = fmaxf(mx0, __shfl_xor_sync(0xffffffffu, mx0, 2));
        mx8 = fmaxf(mx8, __shfl_xor_sync(0xffffffffu, mx8, 1));
        mx8 = fmaxf(mx8, __shfl_xor_sync(0xffffffffu, mx8, 2));
        const float mn0 = fmaxf(m0, mx0), mn8 = fmaxf(m8, mx8);
        const float a0 = fast_exp(m0 - mn0), a8 = fast_exp(m8 - mn8);
        m0 = mn0; m8 = mn8;

        uint32_t pr0[8], pr8[8], qr0[8], qr8[8];
        float s0 = 0.f, s8 = 0.f;
#pragma unroll
        for (int j = 0; j < 8; j++) {
            float p0 = fast_exp(sfr[j][0] - mn0);
            float p1 = fast_exp(sfr[j][1] - mn0);
            float p2 = fast_exp(sfr[j][2] - mn8);
            float p3 = fast_exp(sfr[j][3] - mn8);
            s0 += p0 + p1; s8 += p2 + p3;
            __nv_bfloat162 h01 = __float22bfloat162_rn(make_float2(p0, p1));
            __nv_bfloat162 h23 = __float22bfloat162_rn(make_float2(p2, p3));
            float2 f01 = __bfloat1622float2(h01);
            float2 f23 = __bfloat1622float2(h23);
            __nv_bfloat162 l01 = __float22bfloat162_rn(make_float2(p0 - f01.x, p1 - f01.y));
            __nv_bfloat162 l23 = __float22bfloat162_rn(make_float2(p2 - f23.x, p3 - f23.y));
            pr0[j] = *(uint32_t*)&h01; pr8[j] = *(uint32_t*)&h23;
            qr0[j] = *(uint32_t*)&l01; qr8[j] = *(uint32_t*)&l23;
        }
        s0 += __shfl_xor_sync(0xffffffffu, s0, 1);
        s0 += __shfl_xor_sync(0xffffffffu, s0, 2);
        s8 += __shfl_xor_sync(0xffffffffu, s8, 1);
        s8 += __shfl_xor_sync(0xffffffffu, s8, 2);
        l0 = l0 * a0 + s0;
        l8 = l8 * a8 + s8;
#pragma unroll
        for (int nf = 0; nf < 8; nf++) {
            o_acc[nf][0] *= a0; o_acc[nf][1] *= a0;
            o_acc[nf][2] *= a8; o_acc[nf][3] *= a8;
        }

        // ---- O += P @ V  (ph*vh + ph*vl + pl*vh) ----
#pragma unroll
        for (int ks = 0; ks < 4; ks++) {
            uint32_t vh[4][4], vl[4][4];
#pragma unroll
            for (int nh = 0; nh < 4; nh++) {
                const uint32_t ro = swz((uint32_t)(ks * 16) * 128 + lrow + nh * 32 + lseg);
                ldsm_x4_t(vh[nh], st + 8192  + ro);
                ldsm_x4_t(vl[nh], st + 16384 + ro);
            }
            uint32_t ah[4] = {pr0[2 * ks], pr8[2 * ks], pr0[2 * ks + 1], pr8[2 * ks + 1]};
            uint32_t al[4] = {qr0[2 * ks], qr8[2 * ks], qr0[2 * ks + 1], qr8[2 * ks + 1]};
#pragma unroll
            for (int nf = 0; nf < 8; nf++) {
                uint32_t b0 = vh[nf >> 1][(nf & 1) * 2];
                uint32_t b1 = vh[nf >> 1][(nf & 1) * 2 + 1];
                uint32_t c0 = vl[nf >> 1][(nf & 1) * 2];
                uint32_t c1 = vl[nf >> 1][(nf & 1) * 2 + 1];
                mma_bf16(o_acc[nf], ah, b0, b1);
                mma_bf16(o_acc[nf], ah, c0, c1);
                mma_bf16(o_acc[nf], al, b0, b1);
            }
        }
    }

    // ---- epilogue: normalize, tf32-round, fp32 store [B*S, D] ----
    const float i0 = 1.f / l0, i8 = 1.f / l8;
    const int b = bh / HEADS, h = bh % HEADS;
    const int r0g = q0 + wid * 16 + (lid >> 2);
#pragma unroll
    for (int nf = 0; nf < 8; nf++) {
        const int d0 = nf * 8 + (lid & 3) * 2;
        float2 v0 = make_float2(rna_tf32(o_acc[nf][0] * i0), rna_tf32(o_acc[nf][1] * i0));
        float2 v1 = make_float2(rna_tf32(o_acc[nf][2] * i8), rna_tf32(o_acc[nf][3] * i8));
        *(float2*)(outf + (size_t)(b * S_LEN + r0g)     * EMBED + h * HDIM + d0) = v0;
        *(float2*)(outf + (size_t)(b * S_LEN + r0g + 8) * EMBED + h * HDIM + d0) = v1;
    }
}

// ---------------------------------------------------------------------------
extern "C" void kernel_launch(void* const* d_in, const int* in_sizes, int n_in,
                              void* d_out, int out_size)
{
    const float* X     = (const float*)d_in[0];
    const float* W_qkv = (const float*)d_in[3];
    const float* b_qkv = (const float*)d_in[4];
    const float* W_out = (const float*)d_in[5];
    const float* b_out = (const float*)d_in[6];
    float* out = (float*)d_out;

    float *qkv, *xr, *wqr, *wor, *att;
    __nv_bfloat16 *Qb, *Kb, *Vh, *Vl;
    cudaGetSymbolAddress((void**)&qkv, g_qkv);
    cudaGetSymbolAddress((void**)&xr,  g_xr);
    cudaGetSymbolAddress((void**)&wqr, g_wqr);
    cudaGetSymbolAddress((void**)&wor, g_wor);
    cudaGetSymbolAddress((void**)&att, g_att);
    cudaGetSymbolAddress((void**)&Qb,  g_Qb);
    cudaGetSymbolAddress((void**)&Kb,  g_Kb);
    cudaGetSymbolAddress((void**)&Vh,  g_Vh);
    cudaGetSymbolAddress((void**)&Vl,  g_Vl);

    cudaFuncSetAttribute(gemm_tf32_mma,
                         cudaFuncAttributeMaxDynamicSharedMemorySize, GEMM_SMEM);
    cudaFuncSetAttribute(attn_tc,
                         cudaFuncAttributeMaxDynamicSharedMemorySize, ATT_SMEM);

    {   // tf32 pre-rounding
        round_tf32<<<(MTOT * EMBED / 4 + 255) / 256, 256>>>(X, xr, MTOT * EMBED / 4);
        round_tf32<<<(QKV_DIM * EMBED / 4 + 255) / 256, 256>>>(W_qkv, wqr, QKV_DIM * EMBED / 4);
        round_tf32<<<(EMBED * EMBED / 4 + 255) / 256, 256>>>(W_out, wor, EMBED * EMBED / 4);
    }
    {   // QKV projection (tf32 tensor cores)
        dim3 grid(QKV_DIM / 128, MTOT / 128);
        gemm_tf32_mma<<<grid, 256, GEMM_SMEM>>>(xr, wqr, b_qkv, qkv, QKV_DIM);
    }
    {   // fp32 qkv -> head-contiguous bf16 Q/K/Vhi/Vlo
        int n = MTOT * 768;
        prep_qkv<<<(n + 255) / 256, 256>>>(qkv, Qb, Kb, Vh, Vl);
    }
    {   // tensor-core flash attention -> tf32-rounded fp32
        dim3 grid(S_LEN / 128, BATCH * HEADS);
        attn_tc<<<grid, 256, ATT_SMEM>>>(Qb, Kb, Vh, Vl, att);
    }
    {   // output projection (tf32 tensor cores)
        dim3 grid(EMBED / 128, MTOT / 128);
        gemm_tf32_mma<<<grid, 256, GEMM_SMEM>>>(att, wor, b_out, out, EMBED);
    }
}

// round 7
// speedup vs baseline: 4.8218x; 1.0314x over previous
#include <cuda_runtime.h>
#include <cuda_bf16.h>
#include <cstdint>
#include <cstddef>

#define EMBED   1024
#define S_LEN   2048
#define BATCH   4
#define HEADS   16
#define HDIM    64
#define QKV_DIM 3072
#define MTOT    8192          // BATCH * S_LEN

// ---------------------------------------------------------------------------
// Scratch (device globals; allocation-free rule)
// ---------------------------------------------------------------------------
__device__ __align__(128) float g_xr [(size_t)MTOT * EMBED];     // X tf32-rounded
__device__ __align__(128) float g_wqr[(size_t)QKV_DIM * EMBED];
__device__ __align__(128) float g_wor[(size_t)EMBED * EMBED];
__device__ __align__(128) float g_att[(size_t)MTOT * EMBED];     // attn out (tf32-rounded)
// head-contiguous attention operands [B*H, S, 64] bf16
__device__ __align__(128) __nv_bfloat16 g_Qb[(size_t)MTOT * EMBED];
__device__ __align__(128) __nv_bfloat16 g_Kb[(size_t)MTOT * EMBED];
__device__ __align__(128) __nv_bfloat16 g_Vh[(size_t)MTOT * EMBED];
__device__ __align__(128) __nv_bfloat16 g_Vl[(size_t)MTOT * EMBED];

// ---------------------------------------------------------------------------
__device__ __forceinline__ uint32_t smem_u32(const void* p) {
    uint32_t a;
    asm("{ .reg .u64 t; cvta.to.shared.u64 t, %1; cvt.u32.u64 %0, t; }" : "=r"(a) : "l"(p));
    return a;
}
__device__ __forceinline__ uint32_t swz(uint32_t off) {
    return off ^ ((off >> 3) & 0x70);
}
__device__ __forceinline__ void ldsm_x4(uint32_t* r, uint32_t addr) {
    asm volatile("ldmatrix.sync.aligned.m8n8.x4.shared.b16 {%0,%1,%2,%3}, [%4];"
                 : "=r"(r[0]), "=r"(r[1]), "=r"(r[2]), "=r"(r[3]) : "r"(addr));
}
__device__ __forceinline__ void ldsm_x4_t(uint32_t* r, uint32_t addr) {
    asm volatile("ldmatrix.sync.aligned.m8n8.x4.trans.shared.b16 {%0,%1,%2,%3}, [%4];"
                 : "=r"(r[0]), "=r"(r[1]), "=r"(r[2]), "=r"(r[3]) : "r"(addr));
}
__device__ __forceinline__ void mma_bf16(float* d, const uint32_t* a,
                                         uint32_t b0, uint32_t b1) {
    asm volatile(
        "mma.sync.aligned.m16n8k16.row.col.f32.bf16.bf16.f32 "
        "{%0,%1,%2,%3}, {%4,%5,%6,%7}, {%8,%9}, {%0,%1,%2,%3};"
        : "+f"(d[0]), "+f"(d[1]), "+f"(d[2]), "+f"(d[3])
        : "r"(a[0]), "r"(a[1]), "r"(a[2]), "r"(a[3]), "r"(b0), "r"(b1));
}
__device__ __forceinline__ void mma_tf32(float* d, const uint32_t* a,
                                         uint32_t b0, uint32_t b1) {
    asm volatile(
        "mma.sync.aligned.m16n8k8.row.col.f32.tf32.tf32.f32 "
        "{%0,%1,%2,%3}, {%4,%5,%6,%7}, {%8,%9}, {%0,%1,%2,%3};"
        : "+f"(d[0]), "+f"(d[1]), "+f"(d[2]), "+f"(d[3])
        : "r"(a[0]), "r"(a[1]), "r"(a[2]), "r"(a[3]), "r"(b0), "r"(b1));
}
__device__ __forceinline__ float rna_tf32(float x) {
    uint32_t r;
    asm("cvt.rna.tf32.f32 %0, %1;" : "=r"(r) : "f"(x));
    return __uint_as_float(r);
}
__device__ __forceinline__ float fast_exp(float x) {
    x = fmaxf(x, -80.f);
    float y = x * 1.4426950408889634f;
    float t = y + 12582912.f;
    int   k = __float_as_int(t) - 0x4B400000;
    float f = y - (t - 12582912.f);
    float c = f * 0.6931471805599453f;
    float p = 1.f + c * (1.f + c * (0.5f + c * (0.166666667f +
                  c * (0.0416666667f + c * 0.00833333f))));
    return __int_as_float(__float_as_int(p) + (k << 23));
}

// ---------------------------------------------------------------------------
// single-pass tf32 pre-rounding of X, W_qkv, W_out
// ---------------------------------------------------------------------------
#define N4_X  (MTOT * EMBED / 4)
#define N4_WQ (QKV_DIM * EMBED / 4)
#define N4_WO (EMBED * EMBED / 4)
__global__ void round_all(const float* __restrict__ X, float* __restrict__ xr,
                          const float* __restrict__ Wq, float* __restrict__ wqr,
                          const float* __restrict__ Wo, float* __restrict__ wor)
{
    int i = blockIdx.x * blockDim.x + threadIdx.x;
    const float4* src; float4* dst; int j;
    if (i < N4_X)              { src = (const float4*)X;  dst = (float4*)xr;  j = i; }
    else if (i < N4_X + N4_WQ) { src = (const float4*)Wq; dst = (float4*)wqr; j = i - N4_X; }
    else if (i < N4_X + N4_WQ + N4_WO)
                               { src = (const float4*)Wo; dst = (float4*)wor; j = i - N4_X - N4_WQ; }
    else return;
    float4 v = src[j];
    v.x = rna_tf32(v.x); v.y = rna_tf32(v.y);
    v.z = rna_tf32(v.z); v.w = rna_tf32(v.w);
    dst[j] = v;
}

// ---------------------------------------------------------------------------
// tf32 GEMM mainloop (shared by both projection kernels)
// 128x128 CTA tile, BK=32 floats, SW128, 3-stage cp.async, 8 warps 2x4.
// ---------------------------------------------------------------------------
#define GK         1024
#define BKF        32
#define NITF       (GK / BKF)
#define TILE_B     16384
#define STAGE_B    (2 * TILE_B)
#define GSTAGES    3
#define GEMM_SMEM  (GSTAGES * STAGE_B)

__device__ __forceinline__ void fill_stage_f(uint32_t sb, int s, int c, int tid,
                                             const float* __restrict__ A,
                                             const float* __restrict__ B,
                                             int m0, int n0) {
    const uint32_t stage = sb + s * STAGE_B;
#pragma unroll
    for (int i = 0; i < 8; i++) {
        int seg  = i * 256 + tid;
        int side = seg >> 10;
        int r    = (seg & 1023) >> 3;
        int sc   = seg & 7;
        const float* src = side ? (B + (size_t)(n0 + r) * GK)
                                : (A + (size_t)(m0 + r) * GK);
        const char* g = (const char*)(src + c * BKF) + sc * 16;
        uint32_t d = stage + side * TILE_B + swz((uint32_t)(r * 128 + sc * 16));
        asm volatile("cp.async.cg.shared.global [%0], [%1], 16;" :: "r"(d), "l"(g));
    }
}

__device__ __forceinline__ void gemm_mainloop(uint32_t sb,
                                              const float* __restrict__ A,
                                              const float* __restrict__ B,
                                              int m0, int n0, int tid,
                                              int wm, int wn,
                                              float (&acc)[4][4][4])
{
#pragma unroll
    for (int mf = 0; mf < 4; mf++)
#pragma unroll
        for (int nf = 0; nf < 4; nf++)
#pragma unroll
            for (int k = 0; k < 4; k++) acc[mf][nf][k] = 0.f;

    const int lid = tid & 31;
    const uint32_t lrow = (uint32_t)(lid & 15) * 128;
    const uint32_t lseg = (uint32_t)(lid >> 4) * 16;

    fill_stage_f(sb, 0, 0, tid, A, B, m0, n0);
    asm volatile("cp.async.commit_group;");
    fill_stage_f(sb, 1, 1, tid, A, B, m0, n0);
    asm volatile("cp.async.commit_group;");

    uint32_t afr[2][4][4], bfr[2][2][4];

    for (int c = 0; c < NITF; c++) {
        asm volatile("cp.async.wait_group 1;");
        __syncthreads();
        const int cn = c + 2;
        if (cn < NITF) fill_stage_f(sb, cn % GSTAGES, cn, tid, A, B, m0, n0);
        asm volatile("cp.async.commit_group;");

        const uint32_t aBase = sb + (c % GSTAGES) * STAGE_B;
        const uint32_t bBase = aBase + TILE_B;

#pragma unroll
        for (int mf = 0; mf < 4; mf++)
            ldsm_x4(afr[0][mf], aBase + swz((uint32_t)(wm * 64 + mf * 16) * 128 + lrow + lseg));
#pragma unroll
        for (int nh = 0; nh < 2; nh++)
            ldsm_x4(bfr[0][nh], bBase + swz((uint32_t)(wn * 32 + nh * 16) * 128 + lrow + lseg));

#pragma unroll
        for (int ks = 0; ks < 4; ks++) {
            if (ks < 3) {
                const uint32_t koff = (uint32_t)(ks + 1) * 32 + lseg;
                const int nb = (ks + 1) & 1;
#pragma unroll
                for (int mf = 0; mf < 4; mf++)
                    ldsm_x4(afr[nb][mf], aBase + swz((uint32_t)(wm * 64 + mf * 16) * 128 + lrow + koff));
#pragma unroll
                for (int nh = 0; nh < 2; nh++)
                    ldsm_x4(bfr[nb][nh], bBase + swz((uint32_t)(wn * 32 + nh * 16) * 128 + lrow + koff));
            }
            const int cb = ks & 1;
#pragma unroll
            for (int mf = 0; mf < 4; mf++)
#pragma unroll
                for (int nf = 0; nf < 4; nf++)
                    mma_tf32(acc[mf][nf], afr[cb][mf],
                             bfr[cb][nf >> 1][nf & 1], bfr[cb][nf >> 1][2 + (nf & 1)]);
        }
    }
    __syncthreads();
}

// Projection 1: QKV GEMM, fused epilogue -> Qb (scaled) / Kb / Vh / Vl bf16
__global__ __launch_bounds__(256)
void gemm_qkv_fused(const float* __restrict__ A, const float* __restrict__ B,
                    const float* __restrict__ bias,
                    __nv_bfloat16* __restrict__ Qb, __nv_bfloat16* __restrict__ Kb,
                    __nv_bfloat16* __restrict__ Vh, __nv_bfloat16* __restrict__ Vl)
{
    extern __shared__ char smem[];
    const uint32_t sb = smem_u32(smem);
    const int tid = threadIdx.x, wid = tid >> 5, lid = tid & 31;
    const int wm = wid >> 2, wn = wid & 3;
    const int m0 = blockIdx.y * 128;
    const int n0 = blockIdx.x * 128;

    float acc[4][4][4];
    gemm_mainloop(sb, A, B, m0, n0, tid, wm, wn, acc);

#pragma unroll
    for (int mf = 0; mf < 4; mf++) {
        const int row = m0 + wm * 64 + mf * 16 + (lid >> 2);
#pragma unroll
        for (int nf = 0; nf < 4; nf++) {
            const int col  = n0 + wn * 32 + nf * 8 + (lid & 3) * 2;
            const int part = col >> 10;
            const int hd   = col & 1023;
            const int h = hd >> 6, d = hd & 63;
            float2 bv = *(const float2*)(bias + col);
#pragma unroll
            for (int rr = 0; rr < 2; rr++) {
                const int r = row + rr * 8;
                const size_t o = ((size_t)((r >> 11) * HEADS + h) * S_LEN + (r & 2047)) * HDIM + d;
                float x0 = acc[mf][nf][rr * 2]     + bv.x;
                float x1 = acc[mf][nf][rr * 2 + 1] + bv.y;
                if (part == 0) {
                    *(__nv_bfloat162*)(Qb + o) =
                        __float22bfloat162_rn(make_float2(x0 * 0.125f, x1 * 0.125f));
                } else if (part == 1) {
                    *(__nv_bfloat162*)(Kb + o) =
                        __float22bfloat162_rn(make_float2(x0, x1));
                } else {
                    __nv_bfloat162 hi = __float22bfloat162_rn(make_float2(x0, x1));
                    float2 f = __bfloat1622float2(hi);
                    *(__nv_bfloat162*)(Vh + o) = hi;
                    *(__nv_bfloat162*)(Vl + o) =
                        __float22bfloat162_rn(make_float2(x0 - f.x, x1 - f.y));
                }
            }
        }
    }
}

// Projection 2: generic fp32-out GEMM + bias
__global__ __launch_bounds__(256)
void gemm_tf32_mma(const float* __restrict__ A, const float* __restrict__ B,
                   const float* __restrict__ bias, float* __restrict__ C, int N)
{
    extern __shared__ char smem[];
    const uint32_t sb = smem_u32(smem);
    const int tid = threadIdx.x, wid = tid >> 5, lid = tid & 31;
    const int wm = wid >> 2, wn = wid & 3;
    const int m0 = blockIdx.y * 128;
    const int n0 = blockIdx.x * 128;

    float acc[4][4][4];
    gemm_mainloop(sb, A, B, m0, n0, tid, wm, wn, acc);

#pragma unroll
    for (int mf = 0; mf < 4; mf++) {
        const int row = m0 + wm * 64 + mf * 16 + (lid >> 2);
#pragma unroll
        for (int nf = 0; nf < 4; nf++) {
            const int col = n0 + wn * 32 + nf * 8 + (lid & 3) * 2;
            float2 bv = *(const float2*)(bias + col);
            float2 v0 = make_float2(acc[mf][nf][0] + bv.x, acc[mf][nf][1] + bv.y);
            float2 v1 = make_float2(acc[mf][nf][2] + bv.x, acc[mf][nf][3] + bv.y);
            *(float2*)(C + (size_t)row * N + col)       = v0;
            *(float2*)(C + (size_t)(row + 8) * N + col) = v1;
        }
    }
}

// ---------------------------------------------------------------------------
// Tensor-core flash attention (bf16 QK, hi/lo-split PV), 2 CTAs/SM target.
// ---------------------------------------------------------------------------
#define ATT_STAGE_B 24576
#define ATT_SMEM    (16384 + 3 * ATT_STAGE_B)
#define NKV         (S_LEN / 64)

__global__ __launch_bounds__(256, 2)
void attn_tc(const __nv_bfloat16* __restrict__ Qb, const __nv_bfloat16* __restrict__ Kb,
             const __nv_bfloat16* __restrict__ Vh, const __nv_bfloat16* __restrict__ Vl,
             float* __restrict__ outf)
{
    extern __shared__ char smem[];
    const uint32_t sb = smem_u32(smem);
    const int tid = threadIdx.x, wid = tid >> 5, lid = tid & 31;
    const int q0 = blockIdx.x * 128;
    const int bh = blockIdx.y;
    const size_t hb = (size_t)bh * S_LEN * HDIM;

    {
        const char* qg = (const char*)(Qb + hb + (size_t)q0 * HDIM);
        for (int i = tid; i < 1024; i += 256) {
            uint32_t d = sb + swz((uint32_t)i * 16);
            asm volatile("cp.async.cg.shared.global [%0], [%1], 16;" :: "r"(d), "l"(qg + i * 16));
        }
        asm volatile("cp.async.commit_group;");
    }
    auto load_kv = [&](int stage, int t) {
        const uint32_t st = sb + 16384 + stage * ATT_STAGE_B;
        const char* kg = (const char*)(Kb + hb + (size_t)t * 64 * HDIM);
        const char* hg = (const char*)(Vh + hb + (size_t)t * 64 * HDIM);
        const char* lg = (const char*)(Vl + hb + (size_t)t * 64 * HDIM);
        for (int i = tid; i < 512; i += 256) {
            uint32_t o = swz((uint32_t)i * 16);
            asm volatile("cp.async.cg.shared.global [%0], [%1], 16;" :: "r"(st + o),         "l"(kg + i * 16));
            asm volatile("cp.async.cg.shared.global [%0], [%1], 16;" :: "r"(st + 8192 + o),  "l"(hg + i * 16));
            asm volatile("cp.async.cg.shared.global [%0], [%1], 16;" :: "r"(st + 16384 + o), "l"(lg + i * 16));
        }
    };
    load_kv(0, 0);
    asm volatile("cp.async.commit_group;");
    load_kv(1, 1);
    asm volatile("cp.async.commit_group;");

    asm volatile("cp.async.wait_group 2;");
    __syncthreads();

    const uint32_t lrow = (uint32_t)(lid & 15) * 128;
    const uint32_t lseg = (uint32_t)(lid >> 4) * 16;

    uint32_t qfr[4][4];
#pragma unroll
    for (int ks = 0; ks < 4; ks++)
        ldsm_x4(qfr[ks], sb + swz((uint32_t)(wid * 16) * 128 + lrow + ks * 32 + lseg));

    float o_acc[8][4];
#pragma unroll
    for (int nf = 0; nf < 8; nf++)
#pragma unroll
        for (int k = 0; k < 4; k++) o_acc[nf][k] = 0.f;
    float m0 = -1e30f, m8 = -1e30f, l0 = 0.f, l8 = 0.f;

    for (int t = 0; t < NKV; t++) {
        asm volatile("cp.async.wait_group 1;");
        __syncthreads();
        if (t + 2 < NKV) load_kv((t + 2) % 3, t + 2);
        asm volatile("cp.async.commit_group;");

        const uint32_t st = sb + 16384 + (t % 3) * ATT_STAGE_B;

        float sfr[8][4];
#pragma unroll
        for (int nf = 0; nf < 8; nf++)
#pragma unroll
            for (int k = 0; k < 4; k++) sfr[nf][k] = 0.f;
#pragma unroll
        for (int ks = 0; ks < 4; ks++) {
            uint32_t bfr[4][4];
#pragma unroll
            for (int nh = 0; nh < 4; nh++)
                ldsm_x4(bfr[nh], st + swz((uint32_t)(nh * 16) * 128 + lrow + ks * 32 + lseg));
#pragma unroll
            for (int nf = 0; nf < 8; nf++)
                mma_bf16(sfr[nf], qfr[ks],
                         bfr[nf >> 1][nf & 1], bfr[nf >> 1][2 + (nf & 1)]);
        }

        float mx0 = -1e30f, mx8 = -1e30f;
#pragma unroll
        for (int j = 0; j < 8; j++) {
            mx0 = fmaxf(mx0, fmaxf(sfr[j][0], sfr[j][1]));
            mx8 = fmaxf(mx8, fmaxf(sfr[j][2], sfr[j][3]));
        }
        mx0 = fmaxf(mx0, __shfl_xor_sync(0xffffffffu, mx0, 1));
        mx0 = fmaxf(mx0, __shfl_xor_sync(0xffffffffu, mx0, 2));
        mx8 = fmaxf(mx8, __shfl_xor_sync(0xffffffffu, mx8, 1));
        mx8 = fmaxf(mx8, __shfl_xor_sync(0xffffffffu, mx8, 2));
        const float mn0 = fmaxf(m0, mx0), mn8 = fmaxf(m8, mx8);
        const float a0 = fast_exp(m0 - mn0), a8 = fast_exp(m8 - mn8);
        m0 = mn0; m8 = mn8;

        uint32_t pr0[8], pr8[8], qr0[8], qr8[8];
        float s0 = 0.f, s8 = 0.f;
#pragma unroll
        for (int j = 0; j < 8; j++) {
            float p0 = fast_exp(sfr[j][0] - mn0);
            float p1 = fast_exp(sfr[j][1] - mn0);
            float p2 = fast_exp(sfr[j][2] - mn8);
            float p3 = fast_exp(sfr[j][3] - mn8);
            s0 += p0 + p1; s8 += p2 + p3;
            __nv_bfloat162 h01 = __float22bfloat162_rn(make_float2(p0, p1));
            __nv_bfloat162 h23 = __float22bfloat162_rn(make_float2(p2, p3));
            float2 f01 = __bfloat1622float2(h01);
            float2 f23 = __bfloat1622float2(h23);
            __nv_bfloat162 l01 = __float22bfloat162_rn(make_float2(p0 - f01.x, p1 - f01.y));
            __nv_bfloat162 l23 = __float22bfloat162_rn(make_float2(p2 - f23.x, p3 - f23.y));
            pr0[j] = *(uint32_t*)&h01; pr8[j] = *(uint32_t*)&h23;
            qr0[j] = *(uint32_t*)&l01; qr8[j] = *(uint32_t*)&l23;
        }
        s0 += __shfl_xor_sync(0xffffffffu, s0, 1);
        s0 += __shfl_xor_sync(0xffffffffu, s0, 2);
        s8 += __shfl_xor_sync(0xffffffffu, s8, 1);
        s8 += __shfl_xor_sync(0xffffffffu, s8, 2);
        l0 = l0 * a0 + s0;
        l8 = l8 * a8 + s8;
#pragma unroll
        for (int nf = 0; nf < 8; nf++) {
            o_acc[nf][0] *= a0; o_acc[nf][1] *= a0;
            o_acc[nf][2] *= a8; o_acc[nf][3] *= a8;
        }

#pragma unroll
        for (int ks = 0; ks < 4; ks++) {
            uint32_t vh[4][4], vl[4][4];
#pragma unroll
            for (int nh = 0; nh < 4; nh++) {
                const uint32_t ro = swz((uint32_t)(ks * 16) * 128 + lrow + nh * 32 + lseg);
                ldsm_x4_t(vh[nh], st + 8192  + ro);
                ldsm_x4_t(vl[nh], st + 16384 + ro);
            }
            uint32_t ah[4] = {pr0[2 * ks], pr8[2 * ks], pr0[2 * ks + 1], pr8[2 * ks + 1]};
            uint32_t al[4] = {qr0[2 * ks], qr8[2 * ks], qr0[2 * ks + 1], qr8[2 * ks + 1]};
#pragma unroll
            for (int nf = 0; nf < 8; nf++) {
                uint32_t b0 = vh[nf >> 1][(nf & 1) * 2];
                uint32_t b1 = vh[nf >> 1][(nf & 1) * 2 + 1];
                uint32_t c0 = vl[nf >> 1][(nf & 1) * 2];
                uint32_t c1 = vl[nf >> 1][(nf & 1) * 2 + 1];
                mma_bf16(o_acc[nf], ah, b0, b1);
                mma_bf16(o_acc[nf], ah, c0, c1);
                mma_bf16(o_acc[nf], al, b0, b1);
            }
        }
    }

    const float i0 = 1.f / l0, i8 = 1.f / l8;
    const int b = bh / HEADS, h = bh % HEADS;
    const int r0g = q0 + wid * 16 + (lid >> 2);
#pragma unroll
    for (int nf = 0; nf < 8; nf++) {
        const int d0 = nf * 8 + (lid & 3) * 2;
        float2 v0 = make_float2(rna_tf32(o_acc[nf][0] * i0), rna_tf32(o_acc[nf][1] * i0));
        float2 v1 = make_float2(rna_tf32(o_acc[nf][2] * i8), rna_tf32(o_acc[nf][3] * i8));
        *(float2*)(outf + (size_t)(b * S_LEN + r0g)     * EMBED + h * HDIM + d0) = v0;
        *(float2*)(outf + (size_t)(b * S_LEN + r0g + 8) * EMBED + h * HDIM + d0) = v1;
    }
}

// ---------------------------------------------------------------------------
extern "C" void kernel_launch(void* const* d_in, const int* in_sizes, int n_in,
                              void* d_out, int out_size)
{
    const float* X     = (const float*)d_in[0];
    const float* W_qkv = (const float*)d_in[3];
    const float* b_qkv = (const float*)d_in[4];
    const float* W_out = (const float*)d_in[5];
    const float* b_out = (const float*)d_in[6];
    float* out = (float*)d_out;

    float *xr, *wqr, *wor, *att;
    __nv_bfloat16 *Qb, *Kb, *Vh, *Vl;
    cudaGetSymbolAddress((void**)&xr,  g_xr);
    cudaGetSymbolAddress((void**)&wqr, g_wqr);
    cudaGetSymbolAddress((void**)&wor, g_wor);
    cudaGetSymbolAddress((void**)&att, g_att);
    cudaGetSymbolAddress((void**)&Qb,  g_Qb);
    cudaGetSymbolAddress((void**)&Kb,  g_Kb);
    cudaGetSymbolAddress((void**)&Vh,  g_Vh);
    cudaGetSymbolAddress((void**)&Vl,  g_Vl);

    cudaFuncSetAttribute(gemm_qkv_fused,
                         cudaFuncAttributeMaxDynamicSharedMemorySize, GEMM_SMEM);
    cudaFuncSetAttribute(gemm_tf32_mma,
                         cudaFuncAttributeMaxDynamicSharedMemorySize, GEMM_SMEM);
    cudaFuncSetAttribute(attn_tc,
                         cudaFuncAttributeMaxDynamicSharedMemorySize, ATT_SMEM);

    {   // tf32 pre-rounding (one kernel)
        int n = N4_X + N4_WQ + N4_WO;
        round_all<<<(n + 255) / 256, 256>>>(X, xr, W_qkv, wqr, W_out, wor);
    }
    {   // QKV projection, fused epilogue -> Qb/Kb/Vh/Vl
        dim3 grid(QKV_DIM / 128, MTOT / 128);
        gemm_qkv_fused<<<grid, 256, GEMM_SMEM>>>(xr, wqr, b_qkv, Qb, Kb, Vh, Vl);
    }
    {   // tensor-core flash attention -> tf32-rounded fp32
        dim3 grid(S_LEN / 128, BATCH * HEADS);
        attn_tc<<<grid, 256, ATT_SMEM>>>(Qb, Kb, Vh, Vl, att);
    }
    {   // output projection
        dim3 grid(EMBED / 128, MTOT / 128);
        gemm_tf32_mma<<<grid, 256, GEMM_SMEM>>>(att, wor, b_out, out, EMBED);
    }
}

// round 9
// speedup vs baseline: 5.2891x; 1.0969x over previous
#include <cuda_runtime.h>
#include <cuda_bf16.h>
#include <cstdint>
#include <cstddef>

#define EMBED   1024
#define S_LEN   2048
#define BATCH   4
#define HEADS   16
#define HDIM    64
#define QKV_DIM 3072
#define MTOT    8192          // BATCH * S_LEN

// ---------------------------------------------------------------------------
// Scratch (device globals; allocation-free rule)
// ---------------------------------------------------------------------------
__device__ __align__(128) float g_wqr[(size_t)QKV_DIM * EMBED];  // W_qkv tf32-rounded
__device__ __align__(128) float g_wor[(size_t)EMBED * EMBED];    // W_out tf32-rounded
__device__ __align__(128) float g_att[(size_t)MTOT * EMBED];     // attn out (tf32-rounded)
// head-contiguous attention operands [B*H, S, 64] bf16
__device__ __align__(128) __nv_bfloat16 g_Qb[(size_t)MTOT * EMBED];
__device__ __align__(128) __nv_bfloat16 g_Kb[(size_t)MTOT * EMBED];
__device__ __align__(128) __nv_bfloat16 g_Vh[(size_t)MTOT * EMBED];
__device__ __align__(128) __nv_bfloat16 g_Vl[(size_t)MTOT * EMBED];

// ---------------------------------------------------------------------------
__device__ __forceinline__ uint32_t smem_u32(const void* p) {
    uint32_t a;
    asm("{ .reg .u64 t; cvta.to.shared.u64 t, %1; cvt.u32.u64 %0, t; }" : "=r"(a) : "l"(p));
    return a;
}
__device__ __forceinline__ uint32_t swz(uint32_t off) {
    return off ^ ((off >> 3) & 0x70);
}
__device__ __forceinline__ void ldsm_x4(uint32_t* r, uint32_t addr) {
    asm volatile("ldmatrix.sync.aligned.m8n8.x4.shared.b16 {%0,%1,%2,%3}, [%4];"
                 : "=r"(r[0]), "=r"(r[1]), "=r"(r[2]), "=r"(r[3]) : "r"(addr));
}
__device__ __forceinline__ void ldsm_x4_t(uint32_t* r, uint32_t addr) {
    asm volatile("ldmatrix.sync.aligned.m8n8.x4.trans.shared.b16 {%0,%1,%2,%3}, [%4];"
                 : "=r"(r[0]), "=r"(r[1]), "=r"(r[2]), "=r"(r[3]) : "r"(addr));
}
__device__ __forceinline__ void mma_bf16(float* d, const uint32_t* a,
                                         uint32_t b0, uint32_t b1) {
    asm volatile(
        "mma.sync.aligned.m16n8k16.row.col.f32.bf16.bf16.f32 "
        "{%0,%1,%2,%3}, {%4,%5,%6,%7}, {%8,%9}, {%0,%1,%2,%3};"
        : "+f"(d[0]), "+f"(d[1]), "+f"(d[2]), "+f"(d[3])
        : "r"(a[0]), "r"(a[1]), "r"(a[2]), "r"(a[3]), "r"(b0), "r"(b1));
}
__device__ __forceinline__ void mma_tf32(float* d, const uint32_t* a,
                                         uint32_t b0, uint32_t b1) {
    asm volatile(
        "mma.sync.aligned.m16n8k8.row.col.f32.tf32.tf32.f32 "
        "{%0,%1,%2,%3}, {%4,%5,%6,%7}, {%8,%9}, {%0,%1,%2,%3};"
        : "+f"(d[0]), "+f"(d[1]), "+f"(d[2]), "+f"(d[3])
        : "r"(a[0]), "r"(a[1]), "r"(a[2]), "r"(a[3]), "r"(b0), "r"(b1));
}
__device__ __forceinline__ float rna_tf32(float x) {
    uint32_t r;
    asm("cvt.rna.tf32.f32 %0, %1;" : "=r"(r) : "f"(x));
    return __uint_as_float(r);
}

// ---------------------------------------------------------------------------
// tf32 pre-rounding of the two weight matrices only (X uses hw truncation;
// the resulting -2^-13 multiplicative bias is well inside error budget)
// ---------------------------------------------------------------------------
#define N4_WQ (QKV_DIM * EMBED / 4)
#define N4_WO (EMBED * EMBED / 4)
__global__ void round_wts(const float* __restrict__ Wq, float* __restrict__ wqr,
                          const float* __restrict__ Wo, float* __restrict__ wor)
{
    int i = blockIdx.x * blockDim.x + threadIdx.x;
    const float4* src; float4* dst; int j;
    if (i < N4_WQ)             { src = (const float4*)Wq; dst = (float4*)wqr; j = i; }
    else if (i < N4_WQ + N4_WO){ src = (const float4*)Wo; dst = (float4*)wor; j = i - N4_WQ; }
    else return;
    float4 v = src[j];
    v.x = rna_tf32(v.x); v.y = rna_tf32(v.y);
    v.z = rna_tf32(v.z); v.w = rna_tf32(v.w);
    dst[j] = v;
}

// ---------------------------------------------------------------------------
// tf32 GEMM mainloop (shared). 128x128 CTA tile, BK=32 floats, SW128,
// 3-stage cp.async, 8 warps 2x4, fragment double-buffering.
// ---------------------------------------------------------------------------
#define GK         1024
#define BKF        32
#define NITF       (GK / BKF)
#define TILE_B     16384
#define STAGE_B    (2 * TILE_B)
#define GSTAGES    3
#define GEMM_SMEM  (GSTAGES * STAGE_B)

__device__ __forceinline__ void fill_stage_f(uint32_t sb, int s, int c, int tid,
                                             const float* __restrict__ A,
                                             const float* __restrict__ B,
                                             int m0, int n0) {
    const uint32_t stage = sb + s * STAGE_B;
#pragma unroll
    for (int i = 0; i < 8; i++) {
        int seg  = i * 256 + tid;
        int side = seg >> 10;
        int r    = (seg & 1023) >> 3;
        int sc   = seg & 7;
        const float* src = side ? (B + (size_t)(n0 + r) * GK)
                                : (A + (size_t)(m0 + r) * GK);
        const char* g = (const char*)(src + c * BKF) + sc * 16;
        uint32_t d = stage + side * TILE_B + swz((uint32_t)(r * 128 + sc * 16));
        asm volatile("cp.async.cg.shared.global [%0], [%1], 16;" :: "r"(d), "l"(g));
    }
}

__device__ __forceinline__ void gemm_mainloop(uint32_t sb,
                                              const float* __restrict__ A,
                                              const float* __restrict__ B,
                                              int m0, int n0, int tid,
                                              int wm, int wn,
                                              float (&acc)[4][4][4])
{
#pragma unroll
    for (int mf = 0; mf < 4; mf++)
#pragma unroll
        for (int nf = 0; nf < 4; nf++)
#pragma unroll
            for (int k = 0; k < 4; k++) acc[mf][nf][k] = 0.f;

    const int lid = tid & 31;
    const uint32_t lrow = (uint32_t)(lid & 15) * 128;
    const uint32_t lseg = (uint32_t)(lid >> 4) * 16;

    fill_stage_f(sb, 0, 0, tid, A, B, m0, n0);
    asm volatile("cp.async.commit_group;");
    fill_stage_f(sb, 1, 1, tid, A, B, m0, n0);
    asm volatile("cp.async.commit_group;");

    uint32_t afr[2][4][4], bfr[2][2][4];

    for (int c = 0; c < NITF; c++) {
        asm volatile("cp.async.wait_group 1;");
        __syncthreads();
        const int cn = c + 2;
        if (cn < NITF) fill_stage_f(sb, cn % GSTAGES, cn, tid, A, B, m0, n0);
        asm volatile("cp.async.commit_group;");

        const uint32_t aBase = sb + (c % GSTAGES) * STAGE_B;
        const uint32_t bBase = aBase + TILE_B;

#pragma unroll
        for (int mf = 0; mf < 4; mf++)
            ldsm_x4(afr[0][mf], aBase + swz((uint32_t)(wm * 64 + mf * 16) * 128 + lrow + lseg));
#pragma unroll
        for (int nh = 0; nh < 2; nh++)
            ldsm_x4(bfr[0][nh], bBase + swz((uint32_t)(wn * 32 + nh * 16) * 128 + lrow + lseg));

#pragma unroll
        for (int ks = 0; ks < 4; ks++) {
            if (ks < 3) {
                const uint32_t koff = (uint32_t)(ks + 1) * 32 + lseg;
                const int nb = (ks + 1) & 1;
#pragma unroll
                for (int mf = 0; mf < 4; mf++)
                    ldsm_x4(afr[nb][mf], aBase + swz((uint32_t)(wm * 64 + mf * 16) * 128 + lrow + koff));
#pragma unroll
                for (int nh = 0; nh < 2; nh++)
                    ldsm_x4(bfr[nb][nh], bBase + swz((uint32_t)(wn * 32 + nh * 16) * 128 + lrow + koff));
            }
            const int cb = ks & 1;
#pragma unroll
            for (int mf = 0; mf < 4; mf++)
#pragma unroll
                for (int nf = 0; nf < 4; nf++)
                    mma_tf32(acc[mf][nf], afr[cb][mf],
                             bfr[cb][nf >> 1][nf & 1], bfr[cb][nf >> 1][2 + (nf & 1)]);
        }
    }
    __syncthreads();
}

// Projection 1: QKV GEMM, fused epilogue -> Qb (scaled) / Kb / Vh / Vl bf16
__global__ __launch_bounds__(256)
void gemm_qkv_fused(const float* __restrict__ A, const float* __restrict__ B,
                    const float* __restrict__ bias,
                    __nv_bfloat16* __restrict__ Qb, __nv_bfloat16* __restrict__ Kb,
                    __nv_bfloat16* __restrict__ Vh, __nv_bfloat16* __restrict__ Vl)
{
    extern __shared__ char smem[];
    const uint32_t sb = smem_u32(smem);
    const int tid = threadIdx.x, wid = tid >> 5, lid = tid & 31;
    const int wm = wid >> 2, wn = wid & 3;
    const int m0 = blockIdx.y * 128;
    const int n0 = blockIdx.x * 128;

    float acc[4][4][4];
    gemm_mainloop(sb, A, B, m0, n0, tid, wm, wn, acc);

#pragma unroll
    for (int mf = 0; mf < 4; mf++) {
        const int row = m0 + wm * 64 + mf * 16 + (lid >> 2);
#pragma unroll
        for (int nf = 0; nf < 4; nf++) {
            const int col  = n0 + wn * 32 + nf * 8 + (lid & 3) * 2;
            const int part = col >> 10;
            const int hd   = col & 1023;
            const int h = hd >> 6, d = hd & 63;
            float2 bv = *(const float2*)(bias + col);
#pragma unroll
            for (int rr = 0; rr < 2; rr++) {
                const int r = row + rr * 8;
                const size_t o = ((size_t)((r >> 11) * HEADS + h) * S_LEN + (r & 2047)) * HDIM + d;
                float x0 = acc[mf][nf][rr * 2]     + bv.x;
                float x1 = acc[mf][nf][rr * 2 + 1] + bv.y;
                if (part == 0) {
                    *(__nv_bfloat162*)(Qb + o) =
                        __float22bfloat162_rn(make_float2(x0 * 0.125f, x1 * 0.125f));
                } else if (part == 1) {
                    *(__nv_bfloat162*)(Kb + o) =
                        __float22bfloat162_rn(make_float2(x0, x1));
                } else {
                    __nv_bfloat162 hi = __float22bfloat162_rn(make_float2(x0, x1));
                    float2 f = __bfloat1622float2(hi);
                    *(__nv_bfloat162*)(Vh + o) = hi;
                    *(__nv_bfloat162*)(Vl + o) =
                        __float22bfloat162_rn(make_float2(x0 - f.x, x1 - f.y));
                }
            }
        }
    }
}

// Projection 2: generic fp32-out GEMM + bias
__global__ __launch_bounds__(256)
void gemm_tf32_mma(const float* __restrict__ A, const float* __restrict__ B,
                   const float* __restrict__ bias, float* __restrict__ C, int N)
{
    extern __shared__ char smem[];
    const uint32_t sb = smem_u32(smem);
    const int tid = threadIdx.x, wid = tid >> 5, lid = tid & 31;
    const int wm = wid >> 2, wn = wid & 3;
    const int m0 = blockIdx.y * 128;
    const int n0 = blockIdx.x * 128;

    float acc[4][4][4];
    gemm_mainloop(sb, A, B, m0, n0, tid, wm, wn, acc);

#pragma unroll
    for (int mf = 0; mf < 4; mf++) {
        const int row = m0 + wm * 64 + mf * 16 + (lid >> 2);
#pragma unroll
        for (int nf = 0; nf < 4; nf++) {
            const int col = n0 + wn * 32 + nf * 8 + (lid & 3) * 2;
            float2 bv = *(const float2*)(bias + col);
            float2 v0 = make_float2(acc[mf][nf][0] + bv.x, acc[mf][nf][1] + bv.y);
            float2 v1 = make_float2(acc[mf][nf][2] + bv.x, acc[mf][nf][3] + bv.y);
            *(float2*)(C + (size_t)row * N + col)       = v0;
            *(float2*)(C + (size_t)(row + 8) * N + col) = v1;
        }
    }
}

// ---------------------------------------------------------------------------
// Tensor-core flash attention (bf16 QK, hi/lo-split PV).
// exp via MUFU (__expf) to keep the fma pipe free for the MMA-adjacent math.
// ---------------------------------------------------------------------------
#define ATT_STAGE_B 24576
#define ATT_SMEM    (16384 + 3 * ATT_STAGE_B)
#define NKV         (S_LEN / 64)

__global__ __launch_bounds__(256, 2)
void attn_tc(const __nv_bfloat16* __restrict__ Qb, const __nv_bfloat16* __restrict__ Kb,
             const __nv_bfloat16* __restrict__ Vh, const __nv_bfloat16* __restrict__ Vl,
             float* __restrict__ outf)
{
    extern __shared__ char smem[];
    const uint32_t sb = smem_u32(smem);
    const int tid = threadIdx.x, wid = tid >> 5, lid = tid & 31;
    const int q0 = blockIdx.x * 128;
    const int bh = blockIdx.y;
    const size_t hb = (size_t)bh * S_LEN * HDIM;

    {
        const char* qg = (const char*)(Qb + hb + (size_t)q0 * HDIM);
        for (int i = tid; i < 1024; i += 256) {
            uint32_t d = sb + swz((uint32_t)i * 16);
            asm volatile("cp.async.cg.shared.global [%0], [%1], 16;" :: "r"(d), "l"(qg + i * 16));
        }
        asm volatile("cp.async.commit_group;");
    }
    auto load_kv = [&](int stage, int t) {
        const uint32_t st = sb + 16384 + stage * ATT_STAGE_B;
        const char* kg = (const char*)(Kb + hb + (size_t)t * 64 * HDIM);
        const char* hg = (const char*)(Vh + hb + (size_t)t * 64 * HDIM);
        const char* lg = (const char*)(Vl + hb + (size_t)t * 64 * HDIM);
        for (int i = tid; i < 512; i += 256) {
            uint32_t o = swz((uint32_t)i * 16);
            asm volatile("cp.async.cg.shared.global [%0], [%1], 16;" :: "r"(st + o),         "l"(kg + i * 16));
            asm volatile("cp.async.cg.shared.global [%0], [%1], 16;" :: "r"(st + 8192 + o),  "l"(hg + i * 16));
            asm volatile("cp.async.cg.shared.global [%0], [%1], 16;" :: "r"(st + 16384 + o), "l"(lg + i * 16));
        }
    };
    load_kv(0, 0);
    asm volatile("cp.async.commit_group;");
    load_kv(1, 1);
    asm volatile("cp.async.commit_group;");

    asm volatile("cp.async.wait_group 2;");
    __syncthreads();

    const uint32_t lrow = (uint32_t)(lid & 15) * 128;
    const uint32_t lseg = (uint32_t)(lid >> 4) * 16;

    uint32_t qfr[4][4];
#pragma unroll
    for (int ks = 0; ks < 4; ks++)
        ldsm_x4(qfr[ks], sb + swz((uint32_t)(wid * 16) * 128 + lrow + ks * 32 + lseg));

    float o_acc[8][4];
#pragma unroll
    for (int nf = 0; nf < 8; nf++)
#pragma unroll
        for (int k = 0; k < 4; k++) o_acc[nf][k] = 0.f;
    float m0 = -1e30f, m8 = -1e30f, l0 = 0.f, l8 = 0.f;

    for (int t = 0; t < NKV; t++) {
        asm volatile("cp.async.wait_group 1;");
        __syncthreads();
        if (t + 2 < NKV) load_kv((t + 2) % 3, t + 2);
        asm volatile("cp.async.commit_group;");

        const uint32_t st = sb + 16384 + (t % 3) * ATT_STAGE_B;

        float sfr[8][4];
#pragma unroll
        for (int nf = 0; nf < 8; nf++)
#pragma unroll
            for (int k = 0; k < 4; k++) sfr[nf][k] = 0.f;
#pragma unroll
        for (int ks = 0; ks < 4; ks++) {
            uint32_t bfr[4][4];
#pragma unroll
            for (int nh = 0; nh < 4; nh++)
                ldsm_x4(bfr[nh], st + swz((uint32_t)(nh * 16) * 128 + lrow + ks * 32 + lseg));
#pragma unroll
            for (int nf = 0; nf < 8; nf++)
                mma_bf16(sfr[nf], qfr[ks],
                         bfr[nf >> 1][nf & 1], bfr[nf >> 1][2 + (nf & 1)]);
        }

        float mx0 = -1e30f, mx8 = -1e30f;
#pragma unroll
        for (int j = 0; j < 8; j++) {
            mx0 = fmaxf(mx0, fmaxf(sfr[j][0], sfr[j][1]));
            mx8 = fmaxf(mx8, fmaxf(sfr[j][2], sfr[j][3]));
        }
        mx0 = fmaxf(mx0, __shfl_xor_sync(0xffffffffu, mx0, 1));
        mx0 = fmaxf(mx0, __shfl_xor_sync(0xffffffffu, mx0, 2));
        mx8 = fmaxf(mx8, __shfl_xor_sync(0xffffffffu, mx8, 1));
        mx8 = fmaxf(mx8, __shfl_xor_sync(0xffffffffu, mx8, 2));
        const float mn0 = fmaxf(m0, mx0), mn8 = fmaxf(m8, mx8);
        const float a0 = __expf(m0 - mn0), a8 = __expf(m8 - mn8);
        m0 = mn0; m8 = mn8;

        uint32_t pr0[8], pr8[8], qr0[8], qr8[8];
        float s0 = 0.f, s8 = 0.f;
#pragma unroll
        for (int j = 0; j < 8; j++) {
            float p0 = __expf(sfr[j][0] - mn0);
            float p1 = __expf(sfr[j][1] - mn0);
            float p2 = __expf(sfr[j][2] - mn8);
            float p3 = __expf(sfr[j][3] - mn8);
            s0 += p0 + p1; s8 += p2 + p3;
            __nv_bfloat162 h01 = __float22bfloat162_rn(make_float2(p0, p1));
            __nv_bfloat162 h23 = __float22bfloat162_rn(make_float2(p2, p3));
            float2 f01 = __bfloat1622float2(h01);
            float2 f23 = __bfloat1622float2(h23);
            __nv_bfloat162 l01 = __float22bfloat162_rn(make_float2(p0 - f01.x, p1 - f01.y));
            __nv_bfloat162 l23 = __float22bfloat162_rn(make_float2(p2 - f23.x, p3 - f23.y));
            pr0[j] = *(uint32_t*)&h01; pr8[j] = *(uint32_t*)&h23;
            qr0[j] = *(uint32_t*)&l01; qr8[j] = *(uint32_t*)&l23;
        }
        s0 += __shfl_xor_sync(0xffffffffu, s0, 1);
        s0 += __shfl_xor_sync(0xffffffffu, s0, 2);
        s8 += __shfl_xor_sync(0xffffffffu, s8, 1);
        s8 += __shfl_xor_sync(0xffffffffu, s8, 2);
        l0 = l0 * a0 + s0;
        l8 = l8 * a8 + s8;
#pragma unroll
        for (int nf = 0; nf < 8; nf++) {
            o_acc[nf][0] *= a0; o_acc[nf][1] *= a0;
            o_acc[nf][2] *= a8; o_acc[nf][3] *= a8;
        }

#pragma unroll
        for (int ks = 0; ks < 4; ks++) {
            uint32_t vh[4][4], vl[4][4];
#pragma unroll
            for (int nh = 0; nh < 4; nh++) {
                const uint32_t ro = swz((uint32_t)(ks * 16) * 128 + lrow + nh * 32 + lseg);
                ldsm_x4_t(vh[nh], st + 8192  + ro);
                ldsm_x4_t(vl[nh], st + 16384 + ro);
            }
            uint32_t ah[4] = {pr0[2 * ks], pr8[2 * ks], pr0[2 * ks + 1], pr8[2 * ks + 1]};
            uint32_t al[4] = {qr0[2 * ks], qr8[2 * ks], qr0[2 * ks + 1], qr8[2 * ks + 1]};
#pragma unroll
            for (int nf = 0; nf < 8; nf++) {
                uint32_t b0 = vh[nf >> 1][(nf & 1) * 2];
                uint32_t b1 = vh[nf >> 1][(nf & 1) * 2 + 1];
                uint32_t c0 = vl[nf >> 1][(nf & 1) * 2];
                uint32_t c1 = vl[nf >> 1][(nf & 1) * 2 + 1];
                mma_bf16(o_acc[nf], ah, b0, b1);
                mma_bf16(o_acc[nf], ah, c0, c1);
                mma_bf16(o_acc[nf], al, b0, b1);
            }
        }
    }

    const float i0 = 1.f / l0, i8 = 1.f / l8;
    const int b = bh / HEADS, h = bh % HEADS;
    const int r0g = q0 + wid * 16 + (lid >> 2);
#pragma unroll
    for (int nf = 0; nf < 8; nf++) {
        const int d0 = nf * 8 + (lid & 3) * 2;
        float2 v0 = make_float2(rna_tf32(o_acc[nf][0] * i0), rna_tf32(o_acc[nf][1] * i0));
        float2 v1 = make_float2(rna_tf32(o_acc[nf][2] * i8), rna_tf32(o_acc[nf][3] * i8));
        *(float2*)(outf + (size_t)(b * S_LEN + r0g)     * EMBED + h * HDIM + d0) = v0;
        *(float2*)(outf + (size_t)(b * S_LEN + r0g + 8) * EMBED + h * HDIM + d0) = v1;
    }
}

// ---------------------------------------------------------------------------
extern "C" void kernel_launch(void* const* d_in, const int* in_sizes, int n_in,
                              void* d_out, int out_size)
{
    const float* X     = (const float*)d_in[0];
    const float* W_qkv = (const float*)d_in[3];
    const float* b_qkv = (const float*)d_in[4];
    const float* W_out = (const float*)d_in[5];
    const float* b_out = (const float*)d_in[6];
    float* out = (float*)d_out;

    float *wqr, *wor, *att;
    __nv_bfloat16 *Qb, *Kb, *Vh, *Vl;
    cudaGetSymbolAddress((void**)&wqr, g_wqr);
    cudaGetSymbolAddress((void**)&wor, g_wor);
    cudaGetSymbolAddress((void**)&att, g_att);
    cudaGetSymbolAddress((void**)&Qb,  g_Qb);
    cudaGetSymbolAddress((void**)&Kb,  g_Kb);
    cudaGetSymbolAddress((void**)&Vh,  g_Vh);
    cudaGetSymbolAddress((void**)&Vl,  g_Vl);

    cudaFuncSetAttribute(gemm_qkv_fused,
                         cudaFuncAttributeMaxDynamicSharedMemorySize, GEMM_SMEM);
    cudaFuncSetAttribute(gemm_tf32_mma,
                         cudaFuncAttributeMaxDynamicSharedMemorySize, GEMM_SMEM);
    cudaFuncSetAttribute(attn_tc,
                         cudaFuncAttributeMaxDynamicSharedMemorySize, ATT_SMEM);

    {   // tf32 pre-rounding (weights only; X rounds implicitly in the mma)
        int n = N4_WQ + N4_WO;
        round_wts<<<(n + 255) / 256, 256>>>(W_qkv, wqr, W_out, wor);
    }
    {   // QKV projection, fused epilogue -> Qb/Kb/Vh/Vl
        dim3 grid(QKV_DIM / 128, MTOT / 128);
        gemm_qkv_fused<<<grid, 256, GEMM_SMEM>>>(X, wqr, b_qkv, Qb, Kb, Vh, Vl);
    }
    {   // tensor-core flash attention -> tf32-rounded fp32
        dim3 grid(S_LEN / 128, BATCH * HEADS);
        attn_tc<<<grid, 256, ATT_SMEM>>>(Qb, Kb, Vh, Vl, att);
    }
    {   // output projection
        dim3 grid(EMBED / 128, MTOT / 128);
        gemm_tf32_mma<<<grid, 256, GEMM_SMEM>>>(att, wor, b_out, out, EMBED);
    }
}